// round 13
// baseline (speedup 1.0000x reference)
#include <cuda_runtime.h>
#include <cuda_bf16.h>
#include <cstdint>
#include <cstddef>

#define DEV __device__ __forceinline__

constexpr int NT = 512;   // 16 warps
constexpr int BB = 64;    // batch rows per tile
constexpr int TOTAL_TILES = 256;   // 16384 / 64

// ---- smem layout in 32-bit words (identical to R12) ----
constexpr int B1O = 0, BRO = 64, BZO = 128, BINO = 192, BHNO = 256, B2O = 320;
constexpr int W1H = 352;               // [64][68]
constexpr int W1L = W1H + 4352;
constexpr int WIHH = W1L + 4352;       // [192][36]
constexpr int WIHL = WIHH + 6912;
constexpr int WHH_H = WIHL + 6912;
constexpr int WHH_L = WHH_H + 6912;
constexpr int W2H = WHH_L + 6912;      // [16][36]
constexpr int W2L = W2H + 576;
constexpr int XH  = W2L + 576;         // X hi [64][68]; z1 hi aliases rows (stride 68)
constexpr int XL  = XH + 4352;         // X lo [64][68]; z1 lo aliases rows (stride 68)
constexpr int HNH = XL + 4352;         // h_new hi [64][36]
constexpr int HNL = HNH + 2304;
constexpr int HHq = HNL + 2304;        // h_in hi [64][36]
constexpr int HLq = HHq + 2304;
constexpr int SMEM_WORDS = HLq + 2304; // 55776 words = 223104 B

DEV void split2(float x, float y, uint32_t& hi, uint32_t& lo) {
  __nv_bfloat16 xh = __float2bfloat16(x), yh = __float2bfloat16(y);
  __nv_bfloat16 xl = __float2bfloat16(x - __bfloat162float(xh));
  __nv_bfloat16 yl = __float2bfloat16(y - __bfloat162float(yh));
  hi = (uint32_t)__bfloat16_as_ushort(xh) | ((uint32_t)__bfloat16_as_ushort(yh) << 16);
  lo = (uint32_t)__bfloat16_as_ushort(xl) | ((uint32_t)__bfloat16_as_ushort(yl) << 16);
}
DEV float bfbits2f(uint32_t b) { return __uint_as_float(b << 16); }
DEV float tanhap(float x) {
  float y;
  asm("tanh.approx.f32 %0, %1;" : "=f"(y) : "f"(x));
  return y;
}
DEV float sigm(float x) { return fmaf(tanhap(0.5f * x), 0.5f, 0.5f); }
DEV float tanh_(float x) { return tanhap(x); }

DEV uint32_t smem_u32(const void* p) {
  uint32_t r;
  asm("{ .reg .u64 t; cvta.to.shared.u64 t, %1; cvt.u32.u64 %0, t; }" : "=r"(r) : "l"(p));
  return r;
}
DEV void barg128(int id) { asm volatile("bar.sync %0, 128;" :: "r"(id) : "memory"); }
DEV void barg256(int id) { asm volatile("bar.sync %0, 256;" :: "r"(id) : "memory"); }
DEV void mma16816(float* c, const uint32_t* a, uint32_t b0, uint32_t b1) {
  asm volatile(
      "mma.sync.aligned.m16n8k16.row.col.f32.bf16.bf16.f32 "
      "{%0,%1,%2,%3}, {%4,%5,%6,%7}, {%8,%9}, {%0,%1,%2,%3};"
      : "+f"(c[0]), "+f"(c[1]), "+f"(c[2]), "+f"(c[3])
      : "r"(a[0]), "r"(a[1]), "r"(a[2]), "r"(a[3]), "r"(b0), "r"(b1));
}
DEV void ldsm4(uint32_t* r, uint32_t addr) {
  asm volatile("ldmatrix.sync.aligned.m8n8.x4.shared.b16 {%0,%1,%2,%3}, [%4];"
               : "=r"(r[0]), "=r"(r[1]), "=r"(r[2]), "=r"(r[3]) : "r"(addr));
}
DEV void ldsm2(uint32_t& r0, uint32_t& r1, uint32_t addr) {
  asm volatile("ldmatrix.sync.aligned.m8n8.x2.shared.b16 {%0,%1}, [%2];"
               : "=r"(r0), "=r"(r1) : "r"(addr));
}

__global__ void __launch_bounds__(NT, 1)
rnn_v13_kernel(const float* __restrict__ inputs, const float* __restrict__ hidden,
               const float* __restrict__ W1, const float* __restrict__ b1g,
               const float* __restrict__ Wih, const float* __restrict__ bihg,
               const float* __restrict__ Whh, const float* __restrict__ bhhg,
               const float* __restrict__ W2, const float* __restrict__ b2g,
               float* __restrict__ out_q, float* __restrict__ out_h)
{
  extern __shared__ uint32_t smu[];
  float* smf = (float*)smu;
  const uint32_t sb = smem_u32(smu);
  const int a = blockIdx.y;
  const int tid = threadIdx.x;
  const int w = tid >> 5, lane = tid & 31;
  const int mw = w >> 2, nw = w & 3;          // stage1/3 tiling: 4 groups x 4 n-warps
  const int mg = w >> 3, n8 = w & 7;          // stage2 tiling: 2 supergroups x 8 n-warps
  const int g = lane >> 2, cq = lane & 3;
  const int l15 = lane & 15, lhalf = lane >> 4;
  const int l7 = lane & 7, l8b = (lane >> 3) & 1;
  const int bidA = mw + 1;                    // 128-thread barrier per mw group
  const int bidS = mg + 9;                    // 256-thread barrier per supergroup
  const int gl = nw * 32 + lane;              // 0..127 within mw group
  const int gl2 = (nw & 1) * 32 + lane;       // 0..63 within warp-pair

  // ================= one-time: biases + weights -> bf16 hi/lo =================
  if (tid < 64) {
    smf[B1O + tid]  = b1g[a * 64 + tid];
    smf[BRO + tid]  = bihg[a * 192 + tid]       + bhhg[a * 192 + tid];
    smf[BZO + tid]  = bihg[a * 192 + 64 + tid]  + bhhg[a * 192 + 64 + tid];
    smf[BINO + tid] = bihg[a * 192 + 128 + tid];
    smf[BHNO + tid] = bhhg[a * 192 + 128 + tid];
  } else if (tid < 80) {
    smf[B2O + tid - 64] = b2g[a * 16 + tid - 64];
  }
  {
    const float* w1g = W1 + (size_t)a * 64 * 128;
    #pragma unroll 2
    for (int f = tid; f < 2048; f += NT) {            // W1 [64][128]
      int n = f >> 5, p4 = (f & 31) * 2;
      float4 v = *(const float4*)(w1g + (size_t)n * 128 + p4 * 2);
      uint32_t h0, l0, h1, l1;
      split2(v.x, v.y, h0, l0); split2(v.z, v.w, h1, l1);
      smu[W1H + n * 68 + p4] = h0; smu[W1H + n * 68 + p4 + 1] = h1;
      smu[W1L + n * 68 + p4] = l0; smu[W1L + n * 68 + p4 + 1] = l1;
    }
    const float* wig = Wih + (size_t)a * 192 * 64;
    #pragma unroll 2
    for (int f = tid; f < 3072; f += NT) {            // Wih [192][64]
      int n = f >> 4, p4 = (f & 15) * 2;
      float4 v = *(const float4*)(wig + (size_t)n * 64 + p4 * 2);
      uint32_t h0, l0, h1, l1;
      split2(v.x, v.y, h0, l0); split2(v.z, v.w, h1, l1);
      smu[WIHH + n * 36 + p4] = h0; smu[WIHH + n * 36 + p4 + 1] = h1;
      smu[WIHL + n * 36 + p4] = l0; smu[WIHL + n * 36 + p4 + 1] = l1;
    }
    const float* whg = Whh + (size_t)a * 192 * 64;
    #pragma unroll 2
    for (int f = tid; f < 3072; f += NT) {            // Whh [192][64]
      int n = f >> 4, p4 = (f & 15) * 2;
      float4 v = *(const float4*)(whg + (size_t)n * 64 + p4 * 2);
      uint32_t h0, l0, h1, l1;
      split2(v.x, v.y, h0, l0); split2(v.z, v.w, h1, l1);
      smu[WHH_H + n * 36 + p4] = h0; smu[WHH_H + n * 36 + p4 + 1] = h1;
      smu[WHH_L + n * 36 + p4] = l0; smu[WHH_L + n * 36 + p4 + 1] = l1;
    }
    const float* w2g = W2 + (size_t)a * 16 * 64;
    for (int f = tid; f < 256; f += NT) {             // W2 [16][64]
      int n = f >> 4, p4 = (f & 15) * 2;
      float4 v = *(const float4*)(w2g + (size_t)n * 64 + p4 * 2);
      uint32_t h0, l0, h1, l1;
      split2(v.x, v.y, h0, l0); split2(v.z, v.w, h1, l1);
      smu[W2H + n * 36 + p4] = h0; smu[W2H + n * 36 + p4 + 1] = h1;
      smu[W2L + n * 36 + p4] = l0; smu[W2L + n * 36 + p4 + 1] = l1;
    }
  }

  // ================= prologue: load first tile's X, h =================
  {
    const int b0 = blockIdx.x * BB;
    const float* xg = inputs + ((size_t)b0 * 8 + a) * 128;
    #pragma unroll 4
    for (int f = tid; f < 2048; f += NT) {            // X [64][128]
      int row = f >> 5, p4 = (f & 31) * 2;
      float4 v = *(const float4*)(xg + (size_t)row * 1024 + p4 * 2);
      uint32_t h0, l0, h1, l1;
      split2(v.x, v.y, h0, l0); split2(v.z, v.w, h1, l1);
      smu[XH + row * 68 + p4] = h0; smu[XH + row * 68 + p4 + 1] = h1;
      smu[XL + row * 68 + p4] = l0; smu[XL + row * 68 + p4 + 1] = l1;
    }
    const float* hg = hidden + ((size_t)b0 * 8 + a) * 64;
    #pragma unroll 2
    for (int f = tid; f < 1024; f += NT) {            // h [64][64]
      int row = f >> 4, p4 = (f & 15) * 2;
      float4 v = *(const float4*)(hg + (size_t)row * 512 + p4 * 2);
      uint32_t h0, l0, h1, l1;
      split2(v.x, v.y, h0, l0); split2(v.z, v.w, h1, l1);
      smu[HHq + row * 36 + p4] = h0; smu[HHq + row * 36 + p4 + 1] = h1;
      smu[HLq + row * 36 + p4] = l0; smu[HLq + row * 36 + p4 + 1] = l1;
    }
  }
  __syncthreads();

  // ================= pipelined tile loop =================
  const int G = gridDim.x;

  for (int t = blockIdx.x; t < TOTAL_TILES; t += G) {
    const int b0 = t * BB;
    const int tn = t + G;
    const bool have_next = tn < TOTAL_TILES;
    const int bn = tn * BB;

    // ---- stage 1 (4x4): z1 = relu(X @ W1^T + b1); warp covers n-tiles nw, nw+4 ----
    float acc1[2][4];
    #pragma unroll
    for (int s = 0; s < 2; ++s)
      #pragma unroll
      for (int e = 0; e < 4; ++e) acc1[s][e] = 0.f;

    #pragma unroll
    for (int kc = 0; kc < 8; ++kc) {
      uint32_t ah[4], al[4];
      uint32_t aoff = (uint32_t)(16 * mw + l15) * 68 + kc * 8 + lhalf * 4;
      ldsm4(ah, sb + 4 * (XH + aoff));
      ldsm4(al, sb + 4 * (XL + aoff));
      #pragma unroll
      for (int s = 0; s < 2; ++s) {
        uint32_t boff = (uint32_t)(8 * (nw + 4 * s) + l7) * 68 + kc * 8 + l8b * 4;
        uint32_t bh0, bh1, bl0, bl1;
        ldsm2(bh0, bh1, sb + 4 * (W1H + boff));
        ldsm2(bl0, bl1, sb + 4 * (W1L + boff));
        mma16816(acc1[s], ah, bh0, bh1);
        mma16816(acc1[s], al, bh0, bh1);
        mma16816(acc1[s], ah, bl0, bl1);
      }
    }
    barg128(bidA);   // A: group's X reads done (z1 overwrites this group's X rows)

    // ---- prefetch next tile's X / h (rows of own mw group) ----
    float4 pfx[4], pfh[4];
    if (have_next) {
      const float* xg = inputs + ((size_t)bn * 8 + a) * 128;
      #pragma unroll
      for (int k = 0; k < 4; ++k) {
        int f = gl + k * 128;
        int row = 16 * mw + (f >> 5), p4 = (f & 31) * 2;
        pfx[k] = *(const float4*)(xg + (size_t)row * 1024 + p4 * 2);
      }
      if (nw >= 2) {
        const float* hg = hidden + ((size_t)bn * 8 + a) * 64;
        #pragma unroll
        for (int k = 0; k < 4; ++k) {
          int f = gl2 + k * 64;
          int row = 16 * mw + (f >> 4), p4 = (f & 15) * 2;
          pfh[k] = *(const float4*)(hg + (size_t)row * 512 + p4 * 2);
        }
      }
    }

    // ---- epilogue 1 (4x4): bias+relu -> z1 hi/lo (X-alias, stride 68) ----
    #pragma unroll
    for (int s = 0; s < 2; ++s) {
      int ntile = nw + 4 * s;
      int col = 8 * ntile + 2 * cq;
      int pidx = 4 * ntile + cq;
      float bx = smf[B1O + col], by = smf[B1O + col + 1];
      #pragma unroll
      for (int sr = 0; sr < 2; ++sr) {
        int row = 16 * mw + g + 8 * sr;
        float v0 = fmaxf(acc1[s][2 * sr] + bx, 0.f);
        float v1 = fmaxf(acc1[s][2 * sr + 1] + by, 0.f);
        uint32_t ph, pl;
        split2(v0, v1, ph, pl);
        smu[XH + row * 68 + pidx] = ph;
        smu[XL + row * 68 + pidx] = pl;
      }
    }
    barg256(bidS);   // B: supergroup's z1 visible (stage2 reads both 16-row halves)

    // ---- stage 2 (2x8): warp owns rows 32mg..+31 (2 frags), gates r|z|i_n|h_n
    //      at cols 8*n8..8*n8+7 (ntiles n8, n8+8, n8+16, n8+24) ----
    float acc2[4][2][4];
    #pragma unroll
    for (int j = 0; j < 4; ++j)
      #pragma unroll
      for (int ft = 0; ft < 2; ++ft)
        #pragma unroll
        for (int e = 0; e < 4; ++e) acc2[j][ft][e] = 0.f;

    #pragma unroll
    for (int kc = 0; kc < 4; ++kc) {
      uint32_t zh[2][4], zl[2][4], hh_[2][4], hl_[2][4];
      #pragma unroll
      for (int ft = 0; ft < 2; ++ft) {
        uint32_t zoff = (uint32_t)(32 * mg + 16 * ft + l15) * 68 + kc * 8 + lhalf * 4;
        uint32_t aoff = (uint32_t)(32 * mg + 16 * ft + l15) * 36 + kc * 8 + lhalf * 4;
        ldsm4(zh[ft], sb + 4 * (XH + zoff));
        ldsm4(zl[ft], sb + 4 * (XL + zoff));
        ldsm4(hh_[ft], sb + 4 * (HHq + aoff));
        ldsm4(hl_[ft], sb + 4 * (HLq + aoff));
      }
      uint32_t bbase = (uint32_t)l7 * 36 + kc * 8 + l8b * 4;
      #pragma unroll
      for (int j = 0; j < 4; ++j) {
        if (j < 3) {                        // z1 @ Wih rows 8*n8 + 64*j  (r, z, i_n)
          uint32_t bh0, bh1, bl0, bl1;
          uint32_t o = (uint32_t)(8 * n8 + 64 * j) * 36 + bbase;
          ldsm2(bh0, bh1, sb + 4 * (WIHH + o));
          ldsm2(bl0, bl1, sb + 4 * (WIHL + o));
          #pragma unroll
          for (int ft = 0; ft < 2; ++ft) {
            mma16816(acc2[j][ft], zh[ft], bh0, bh1);
            mma16816(acc2[j][ft], zl[ft], bh0, bh1);
            mma16816(acc2[j][ft], zh[ft], bl0, bl1);
          }
        }
        if (j < 2 || j == 3) {              // h @ Whh rows 8n8+64j (r,z) / 128+8n8 (h_n)
          int n0 = (j < 2) ? (8 * n8 + 64 * j) : (128 + 8 * n8);
          uint32_t bh0, bh1, bl0, bl1;
          uint32_t o = (uint32_t)n0 * 36 + bbase;
          ldsm2(bh0, bh1, sb + 4 * (WHH_H + o));
          ldsm2(bl0, bl1, sb + 4 * (WHH_L + o));
          #pragma unroll
          for (int ft = 0; ft < 2; ++ft) {
            mma16816(acc2[j][ft], hh_[ft], bh0, bh1);
            mma16816(acc2[j][ft], hl_[ft], bh0, bh1);
            mma16816(acc2[j][ft], hh_[ft], bl0, bl1);
          }
        }
      }
    }
    barg256(bidS);   // C: supergroup's z1 / h reads done

    // ---- epilogue 2 (2x8): GRU -> h_new (+gmem); then store next X (mw rows) ----
    {
      int cb = 8 * n8 + 2 * cq;
      int pidx = 4 * n8 + cq;
      float brv0 = smf[BRO + cb],  brv1 = smf[BRO + cb + 1];
      float bzv0 = smf[BZO + cb],  bzv1 = smf[BZO + cb + 1];
      float biv0 = smf[BINO + cb], biv1 = smf[BINO + cb + 1];
      float bnv0 = smf[BHNO + cb], bnv1 = smf[BHNO + cb + 1];
      #pragma unroll
      for (int ft = 0; ft < 2; ++ft) {
        #pragma unroll
        for (int sr = 0; sr < 2; ++sr) {
          int row = 32 * mg + 16 * ft + g + 8 * sr;
          uint32_t uh = smu[HHq + row * 36 + pidx], ul = smu[HLq + row * 36 + pidx];
          float ho0 = bfbits2f(uh & 0xffffu) + bfbits2f(ul & 0xffffu);
          float ho1 = bfbits2f(uh >> 16) + bfbits2f(ul >> 16);
          float rv0 = sigm(acc2[0][ft][2 * sr] + brv0);
          float rv1 = sigm(acc2[0][ft][2 * sr + 1] + brv1);
          float zv0 = sigm(acc2[1][ft][2 * sr] + bzv0);
          float zv1 = sigm(acc2[1][ft][2 * sr + 1] + bzv1);
          float nv0 = tanh_(acc2[2][ft][2 * sr] + biv0 +
                            rv0 * (acc2[3][ft][2 * sr] + bnv0));
          float nv1 = tanh_(acc2[2][ft][2 * sr + 1] + biv1 +
                            rv1 * (acc2[3][ft][2 * sr + 1] + bnv1));
          float hn0 = nv0 + zv0 * (ho0 - nv0);
          float hn1 = nv1 + zv1 * (ho1 - nv1);
          uint32_t ph, pl;
          split2(hn0, hn1, ph, pl);
          smu[HNH + row * 36 + pidx] = ph;
          smu[HNL + row * 36 + pidx] = pl;
          *(float2*)(out_h + ((size_t)(b0 + row) * 8 + a) * 64 + cb) = make_float2(hn0, hn1);
        }
      }
    }
    if (have_next) {
      #pragma unroll
      for (int k = 0; k < 4; ++k) {
        int f = gl + k * 128;
        int row = 16 * mw + (f >> 5), p4 = (f & 31) * 2;
        uint32_t h0, l0, h1, l1;
        split2(pfx[k].x, pfx[k].y, h0, l0); split2(pfx[k].z, pfx[k].w, h1, l1);
        smu[XH + row * 68 + p4] = h0; smu[XH + row * 68 + p4 + 1] = h1;
        smu[XL + row * 68 + p4] = l0; smu[XL + row * 68 + p4 + 1] = l1;
      }
    }
    barg256(bidS);   // D: supergroup's hn + next-X visible

    // ---- stage 3 (4x4, n-warps 0,1) in parallel with next-h store (n-warps 2,3);
    //      no trailing barrier: next iteration's A/B barriers provide ordering ----
    if (nw < 2) {
      float acc3[4] = {0.f, 0.f, 0.f, 0.f};
      #pragma unroll
      for (int kc = 0; kc < 4; ++kc) {
        uint32_t boff = (uint32_t)(8 * nw + l7) * 36 + kc * 8 + l8b * 4;
        uint32_t bh0, bh1, bl0, bl1;
        ldsm2(bh0, bh1, sb + 4 * (W2H + boff));
        ldsm2(bl0, bl1, sb + 4 * (W2L + boff));
        uint32_t aoff = (uint32_t)(16 * mw + l15) * 36 + kc * 8 + lhalf * 4;
        uint32_t ah[4], al[4];
        ldsm4(ah, sb + 4 * (HNH + aoff));
        ldsm4(al, sb + 4 * (HNL + aoff));
        mma16816(acc3, ah, bh0, bh1);
        mma16816(acc3, al, bh0, bh1);
        mma16816(acc3, ah, bl0, bl1);
      }
      int colb = 8 * nw + 2 * cq;
      float bq0 = smf[B2O + colb], bq1 = smf[B2O + colb + 1];
      #pragma unroll
      for (int sr = 0; sr < 2; ++sr) {
        int row = 16 * mw + g + 8 * sr;
        float q0 = acc3[2 * sr] + bq0;
        float q1 = acc3[2 * sr + 1] + bq1;
        *(float2*)(out_q + ((size_t)(b0 + row) * 8 + a) * 16 + colb) = make_float2(q0, q1);
      }
    } else if (have_next) {
      #pragma unroll
      for (int k = 0; k < 4; ++k) {
        int f = gl2 + k * 64;
        int row = 16 * mw + (f >> 4), p4 = (f & 15) * 2;
        uint32_t h0, l0, h1, l1;
        split2(pfh[k].x, pfh[k].y, h0, l0); split2(pfh[k].z, pfh[k].w, h1, l1);
        smu[HHq + row * 36 + p4] = h0; smu[HHq + row * 36 + p4 + 1] = h1;
        smu[HLq + row * 36 + p4] = l0; smu[HLq + row * 36 + p4 + 1] = l1;
      }
    }
  }
}

extern "C" void kernel_launch(void* const* d_in, const int* in_sizes, int n_in,
                              void* d_out, int out_size) {
  (void)n_in; (void)out_size;
  const float* inputs = (const float*)d_in[0];
  const float* hidden = (const float*)d_in[1];
  const float* W1  = (const float*)d_in[2];
  const float* b1  = (const float*)d_in[3];
  const float* Wih = (const float*)d_in[4];
  const float* bih = (const float*)d_in[5];
  const float* Whh = (const float*)d_in[6];
  const float* bhh = (const float*)d_in[7];
  const float* W2  = (const float*)d_in[8];
  const float* b2  = (const float*)d_in[9];

  const int B = in_sizes[0] / (8 * 128);   // 16384
  float* out_q = (float*)d_out;
  float* out_h = out_q + (size_t)B * 8 * 16;

  const size_t smem = (size_t)SMEM_WORDS * 4;   // 223104 B
  cudaFuncSetAttribute(rnn_v13_kernel,
                       cudaFuncAttributeMaxDynamicSharedMemorySize, (int)smem);
  dim3 grid(18, 8, 1);                          // 144 CTAs, strided tiles
  rnn_v13_kernel<<<grid, NT, smem>>>(inputs, hidden, W1, b1, Wih, bih,
                                     Whh, bhh, W2, b2, out_q, out_h);
}

// round 14
// speedup vs baseline: 1.0541x; 1.0541x over previous
#include <cuda_runtime.h>
#include <cuda_bf16.h>
#include <cstdint>
#include <cstddef>

#define DEV __device__ __forceinline__

constexpr int NT = 512;   // 16 warps: 4 m-groups x 4 n-warps
constexpr int BB = 64;    // batch rows per tile
constexpr int TOTAL_TILES = 256;   // 16384 / 64

// ---- smem layout in 32-bit words ----
// Per-tile tensors are row-partitioned by m-group (rows 16*mw..16*mw+15);
// aliased regions share the SAME row stride so group rows stay disjoint.
constexpr int B1O = 0, BRO = 64, BZO = 128, BINO = 192, BHNO = 256, B2O = 320;
constexpr int W1H = 352;               // [64][68]
constexpr int W1L = W1H + 4352;
constexpr int WIHH = W1L + 4352;       // [192][36]
constexpr int WIHL = WIHH + 6912;
constexpr int WHH_H = WIHL + 6912;
constexpr int WHH_L = WHH_H + 6912;
constexpr int W2H = WHH_L + 6912;      // [16][36]
constexpr int W2L = W2H + 576;
constexpr int XH  = W2L + 576;         // X hi [64][68]; z1 hi aliases rows (stride 68)
constexpr int XL  = XH + 4352;         // X lo [64][68]; z1 lo aliases rows (stride 68)
constexpr int HNH = XL + 4352;         // h_new hi [64][36]
constexpr int HNL = HNH + 2304;
constexpr int HHq = HNL + 2304;        // h_in hi [64][36]
constexpr int HLq = HHq + 2304;
constexpr int SMEM_WORDS = HLq + 2304; // 55776 words = 223104 B

DEV void split2(float x, float y, uint32_t& hi, uint32_t& lo) {
  __nv_bfloat16 xh = __float2bfloat16(x), yh = __float2bfloat16(y);
  __nv_bfloat16 xl = __float2bfloat16(x - __bfloat162float(xh));
  __nv_bfloat16 yl = __float2bfloat16(y - __bfloat162float(yh));
  hi = (uint32_t)__bfloat16_as_ushort(xh) | ((uint32_t)__bfloat16_as_ushort(yh) << 16);
  lo = (uint32_t)__bfloat16_as_ushort(xl) | ((uint32_t)__bfloat16_as_ushort(yl) << 16);
}
DEV float bfbits2f(uint32_t b) { return __uint_as_float(b << 16); }
DEV float tanhap(float x) {
  float y;
  asm("tanh.approx.f32 %0, %1;" : "=f"(y) : "f"(x));
  return y;
}
DEV float sigm(float x) { return fmaf(tanhap(0.5f * x), 0.5f, 0.5f); }
DEV float tanh_(float x) { return tanhap(x); }

DEV uint32_t smem_u32(const void* p) {
  uint32_t r;
  asm("{ .reg .u64 t; cvta.to.shared.u64 t, %1; cvt.u32.u64 %0, t; }" : "=r"(r) : "l"(p));
  return r;
}
DEV void barg(int id) {   // group barrier: 4 warps = 128 threads
  asm volatile("bar.sync %0, 128;" :: "r"(id) : "memory");
}
DEV void mma16816(float* c, const uint32_t* a, uint32_t b0, uint32_t b1) {
  asm volatile(
      "mma.sync.aligned.m16n8k16.row.col.f32.bf16.bf16.f32 "
      "{%0,%1,%2,%3}, {%4,%5,%6,%7}, {%8,%9}, {%0,%1,%2,%3};"
      : "+f"(c[0]), "+f"(c[1]), "+f"(c[2]), "+f"(c[3])
      : "r"(a[0]), "r"(a[1]), "r"(a[2]), "r"(a[3]), "r"(b0), "r"(b1));
}
DEV void ldsm4(uint32_t* r, uint32_t addr) {
  asm volatile("ldmatrix.sync.aligned.m8n8.x4.shared.b16 {%0,%1,%2,%3}, [%4];"
               : "=r"(r[0]), "=r"(r[1]), "=r"(r[2]), "=r"(r[3]) : "r"(addr));
}
DEV void ldsm2(uint32_t& r0, uint32_t& r1, uint32_t addr) {
  asm volatile("ldmatrix.sync.aligned.m8n8.x2.shared.b16 {%0,%1}, [%2];"
               : "=r"(r0), "=r"(r1) : "r"(addr));
}

__global__ void __launch_bounds__(NT, 1)
rnn_v14_kernel(const float* __restrict__ inputs, const float* __restrict__ hidden,
               const float* __restrict__ W1, const float* __restrict__ b1g,
               const float* __restrict__ Wih, const float* __restrict__ bihg,
               const float* __restrict__ Whh, const float* __restrict__ bhhg,
               const float* __restrict__ W2, const float* __restrict__ b2g,
               float* __restrict__ out_q, float* __restrict__ out_h)
{
  extern __shared__ uint32_t smu[];
  float* smf = (float*)smu;
  const uint32_t sb = smem_u32(smu);
  const int a = blockIdx.y;
  const int tid = threadIdx.x;
  const int w = tid >> 5, lane = tid & 31;
  const int mw = w >> 2, nw = w & 3;          // group = mw (warps 4mw..4mw+3)
  const int g = lane >> 2, cq = lane & 3;
  const int l15 = lane & 15, lhalf = lane >> 4;
  const int l7 = lane & 7, l8b = (lane >> 3) & 1;
  const int bid = mw + 1;                     // named barrier id per group
  const int gl = nw * 32 + lane;              // 0..127 within group

  // ================= one-time: biases + weights -> bf16 hi/lo =================
  if (tid < 64) {
    smf[B1O + tid]  = b1g[a * 64 + tid];
    smf[BRO + tid]  = bihg[a * 192 + tid]       + bhhg[a * 192 + tid];
    smf[BZO + tid]  = bihg[a * 192 + 64 + tid]  + bhhg[a * 192 + 64 + tid];
    smf[BINO + tid] = bihg[a * 192 + 128 + tid];
    smf[BHNO + tid] = bhhg[a * 192 + 128 + tid];
  } else if (tid < 80) {
    smf[B2O + tid - 64] = b2g[a * 16 + tid - 64];
  }
  {
    const float* w1g = W1 + (size_t)a * 64 * 128;
    #pragma unroll 2
    for (int f = tid; f < 2048; f += NT) {            // W1 [64][128]
      int n = f >> 5, p4 = (f & 31) * 2;
      float4 v = *(const float4*)(w1g + (size_t)n * 128 + p4 * 2);
      uint32_t h0, l0, h1, l1;
      split2(v.x, v.y, h0, l0); split2(v.z, v.w, h1, l1);
      smu[W1H + n * 68 + p4] = h0; smu[W1H + n * 68 + p4 + 1] = h1;
      smu[W1L + n * 68 + p4] = l0; smu[W1L + n * 68 + p4 + 1] = l1;
    }
    const float* wig = Wih + (size_t)a * 192 * 64;
    #pragma unroll 2
    for (int f = tid; f < 3072; f += NT) {            // Wih [192][64]
      int n = f >> 4, p4 = (f & 15) * 2;
      float4 v = *(const float4*)(wig + (size_t)n * 64 + p4 * 2);
      uint32_t h0, l0, h1, l1;
      split2(v.x, v.y, h0, l0); split2(v.z, v.w, h1, l1);
      smu[WIHH + n * 36 + p4] = h0; smu[WIHH + n * 36 + p4 + 1] = h1;
      smu[WIHL + n * 36 + p4] = l0; smu[WIHL + n * 36 + p4 + 1] = l1;
    }
    const float* whg = Whh + (size_t)a * 192 * 64;
    #pragma unroll 2
    for (int f = tid; f < 3072; f += NT) {            // Whh [192][64]
      int n = f >> 4, p4 = (f & 15) * 2;
      float4 v = *(const float4*)(whg + (size_t)n * 64 + p4 * 2);
      uint32_t h0, l0, h1, l1;
      split2(v.x, v.y, h0, l0); split2(v.z, v.w, h1, l1);
      smu[WHH_H + n * 36 + p4] = h0; smu[WHH_H + n * 36 + p4 + 1] = h1;
      smu[WHH_L + n * 36 + p4] = l0; smu[WHH_L + n * 36 + p4 + 1] = l1;
    }
    const float* w2g = W2 + (size_t)a * 16 * 64;
    for (int f = tid; f < 256; f += NT) {             // W2 [16][64]
      int n = f >> 4, p4 = (f & 15) * 2;
      float4 v = *(const float4*)(w2g + (size_t)n * 64 + p4 * 2);
      uint32_t h0, l0, h1, l1;
      split2(v.x, v.y, h0, l0); split2(v.z, v.w, h1, l1);
      smu[W2H + n * 36 + p4] = h0; smu[W2H + n * 36 + p4 + 1] = h1;
      smu[W2L + n * 36 + p4] = l0; smu[W2L + n * 36 + p4 + 1] = l1;
    }
  }

  // ================= prologue: load first tile's X, h =================
  {
    const int b0 = blockIdx.x * BB;
    const float* xg = inputs + ((size_t)b0 * 8 + a) * 128;
    #pragma unroll 4
    for (int f = tid; f < 2048; f += NT) {            // X [64][128]
      int row = f >> 5, p4 = (f & 31) * 2;
      float4 v = *(const float4*)(xg + (size_t)row * 1024 + p4 * 2);
      uint32_t h0, l0, h1, l1;
      split2(v.x, v.y, h0, l0); split2(v.z, v.w, h1, l1);
      smu[XH + row * 68 + p4] = h0; smu[XH + row * 68 + p4 + 1] = h1;
      smu[XL + row * 68 + p4] = l0; smu[XL + row * 68 + p4 + 1] = l1;
    }
    const float* hg = hidden + ((size_t)b0 * 8 + a) * 64;
    #pragma unroll 2
    for (int f = tid; f < 1024; f += NT) {            // h [64][64]
      int row = f >> 4, p4 = (f & 15) * 2;
      float4 v = *(const float4*)(hg + (size_t)row * 512 + p4 * 2);
      uint32_t h0, l0, h1, l1;
      split2(v.x, v.y, h0, l0); split2(v.z, v.w, h1, l1);
      smu[HHq + row * 36 + p4] = h0; smu[HHq + row * 36 + p4 + 1] = h1;
      smu[HLq + row * 36 + p4] = l0; smu[HLq + row * 36 + p4 + 1] = l1;
    }
  }
  __syncthreads();

  // ================= pipelined tile loop (group-scoped barriers) =================
  const int G = gridDim.x;

  for (int t = blockIdx.x; t < TOTAL_TILES; t += G) {
    const int b0 = t * BB;
    const int tn = t + G;
    const bool have_next = tn < TOTAL_TILES;
    const int bn = tn * BB;

    // ---- stage 1: z1 = relu(X @ W1^T + b1); warp covers n-tiles nw, nw+4 ----
    float acc1[2][4];
    #pragma unroll
    for (int s = 0; s < 2; ++s)
      #pragma unroll
      for (int e = 0; e < 4; ++e) acc1[s][e] = 0.f;

    #pragma unroll
    for (int kc = 0; kc < 8; ++kc) {
      uint32_t ah[4], al[4];
      uint32_t aoff = (uint32_t)(16 * mw + l15) * 68 + kc * 8 + lhalf * 4;
      ldsm4(ah, sb + 4 * (XH + aoff));
      ldsm4(al, sb + 4 * (XL + aoff));
      // issue both n-tiles' B loads before the MMAs (deeper load MLP)
      uint32_t bh0[2], bh1[2], bl0[2], bl1[2];
      #pragma unroll
      for (int s = 0; s < 2; ++s) {
        uint32_t boff = (uint32_t)(8 * (nw + 4 * s) + l7) * 68 + kc * 8 + l8b * 4;
        ldsm2(bh0[s], bh1[s], sb + 4 * (W1H + boff));
        ldsm2(bl0[s], bl1[s], sb + 4 * (W1L + boff));
      }
      #pragma unroll
      for (int s = 0; s < 2; ++s) {
        mma16816(acc1[s], ah, bh0[s], bh1[s]);
        mma16816(acc1[s], al, bh0[s], bh1[s]);
        mma16816(acc1[s], ah, bl0[s], bl1[s]);
      }
    }
    barg(bid);   // A: group's X reads done (z1 overwrites this group's X rows)

    // ---- prefetch next tile's X / h (earlier LDG issue), group rows only ----
    float4 pfx[4], pfh[2];
    if (have_next) {
      const float* xg = inputs + ((size_t)bn * 8 + a) * 128;
      #pragma unroll
      for (int k = 0; k < 4; ++k) {
        int f = gl + k * 128;                 // 0..511 within group
        int row = 16 * mw + (f >> 5), p4 = (f & 31) * 2;
        pfx[k] = *(const float4*)(xg + (size_t)row * 1024 + p4 * 2);
      }
      const float* hg = hidden + ((size_t)bn * 8 + a) * 64;
      #pragma unroll
      for (int k = 0; k < 2; ++k) {
        int f = gl + k * 128;                 // 0..255 within group (all 4 warps)
        int row = 16 * mw + (f >> 4), p4 = (f & 15) * 2;
        pfh[k] = *(const float4*)(hg + (size_t)row * 512 + p4 * 2);
      }
    }

    // ---- epilogue 1: bias+relu -> z1 hi/lo (row-consistent alias: stride 68) ----
    #pragma unroll
    for (int s = 0; s < 2; ++s) {
      int ntile = nw + 4 * s;
      int col = 8 * ntile + 2 * cq;
      int pidx = 4 * ntile + cq;              // z1 col word 0..31
      float bx = smf[B1O + col], by = smf[B1O + col + 1];
      #pragma unroll
      for (int sr = 0; sr < 2; ++sr) {
        int row = 16 * mw + g + 8 * sr;
        float v0 = fmaxf(acc1[s][2 * sr] + bx, 0.f);
        float v1 = fmaxf(acc1[s][2 * sr + 1] + by, 0.f);
        uint32_t ph, pl;
        split2(v0, v1, ph, pl);
        smu[XH + row * 68 + pidx] = ph;
        smu[XL + row * 68 + pidx] = pl;
      }
    }
    barg(bid);   // B: group's z1 visible

    // ---- stage 2: gate GEMMs. N-space 256 = [r|z|i_n|h_n]; warp owns ntile = nw + 4j ----
    float acc2[8][4];
    #pragma unroll
    for (int j = 0; j < 8; ++j)
      #pragma unroll
      for (int e = 0; e < 4; ++e) acc2[j][e] = 0.f;

    #pragma unroll
    for (int kc = 0; kc < 4; ++kc) {
      uint32_t zh[4], zl[4], hh_[4], hl_[4];
      uint32_t zoff = (uint32_t)(16 * mw + l15) * 68 + kc * 8 + lhalf * 4;  // z1: stride 68
      uint32_t aoff = (uint32_t)(16 * mw + l15) * 36 + kc * 8 + lhalf * 4;  // h: stride 36
      ldsm4(zh, sb + 4 * (XH + zoff));
      ldsm4(zl, sb + 4 * (XL + zoff));
      ldsm4(hh_, sb + 4 * (HHq + aoff));
      ldsm4(hl_, sb + 4 * (HLq + aoff));
      uint32_t bbase = (uint32_t)l7 * 36 + kc * 8 + l8b * 4;
      #pragma unroll
      for (int j = 0; j < 8; ++j) {
        int ntile = nw + 4 * j;
        const bool do_i = (ntile < 24);
        const bool do_h = (ntile < 16 || ntile >= 24);
        uint32_t ih0, ih1, il0, il1, hb0, hb1, lb0, lb1;
        if (do_i) {                         // load Wih fragments
          uint32_t o = (uint32_t)(8 * ntile) * 36 + bbase;
          ldsm2(ih0, ih1, sb + 4 * (WIHH + o));
          ldsm2(il0, il1, sb + 4 * (WIHL + o));
        }
        if (do_h) {                         // load Whh fragments (issued before MMAs)
          int n0 = (ntile < 16) ? 8 * ntile : 8 * ntile - 64;
          uint32_t o = (uint32_t)n0 * 36 + bbase;
          ldsm2(hb0, hb1, sb + 4 * (WHH_H + o));
          ldsm2(lb0, lb1, sb + 4 * (WHH_L + o));
        }
        if (do_i) {
          mma16816(acc2[j], zh, ih0, ih1);
          mma16816(acc2[j], zl, ih0, ih1);
          mma16816(acc2[j], zh, il0, il1);
        }
        if (do_h) {
          mma16816(acc2[j], hh_, hb0, hb1);
          mma16816(acc2[j], hl_, hb0, hb1);
          mma16816(acc2[j], hh_, lb0, lb1);
        }
      }
    }
    barg(bid);   // C: group's z1 / h reads done

    // ---- epilogue 2: GRU -> h_new (+gmem); store next X (group rows) ----
    #pragma unroll
    for (int s = 0; s < 2; ++s) {
      int ntile = nw + 4 * s;
      int cb = 8 * ntile + 2 * cq;
      int pidx = 4 * ntile + cq;
      float brv0 = smf[BRO + cb],  brv1 = smf[BRO + cb + 1];
      float bzv0 = smf[BZO + cb],  bzv1 = smf[BZO + cb + 1];
      float biv0 = smf[BINO + cb], biv1 = smf[BINO + cb + 1];
      float bnv0 = smf[BHNO + cb], bnv1 = smf[BHNO + cb + 1];
      #pragma unroll
      for (int sr = 0; sr < 2; ++sr) {
        int row = 16 * mw + g + 8 * sr;
        uint32_t uh = smu[HHq + row * 36 + pidx], ul = smu[HLq + row * 36 + pidx];
        float ho0 = bfbits2f(uh & 0xffffu) + bfbits2f(ul & 0xffffu);
        float ho1 = bfbits2f(uh >> 16) + bfbits2f(ul >> 16);
        float rv0 = sigm(acc2[s][2 * sr] + brv0);
        float rv1 = sigm(acc2[s][2 * sr + 1] + brv1);
        float zv0 = sigm(acc2[2 + s][2 * sr] + bzv0);
        float zv1 = sigm(acc2[2 + s][2 * sr + 1] + bzv1);
        float nv0 = tanh_(acc2[4 + s][2 * sr] + biv0 +
                          rv0 * (acc2[6 + s][2 * sr] + bnv0));
        float nv1 = tanh_(acc2[4 + s][2 * sr + 1] + biv1 +
                          rv1 * (acc2[6 + s][2 * sr + 1] + bnv1));
        float hn0 = nv0 + zv0 * (ho0 - nv0);
        float hn1 = nv1 + zv1 * (ho1 - nv1);
        uint32_t ph, pl;
        split2(hn0, hn1, ph, pl);
        smu[HNH + row * 36 + pidx] = ph;
        smu[HNL + row * 36 + pidx] = pl;
        *(float2*)(out_h + ((size_t)(b0 + row) * 8 + a) * 64 + cb) = make_float2(hn0, hn1);
      }
    }
    if (have_next) {
      #pragma unroll
      for (int k = 0; k < 4; ++k) {
        int f = gl + k * 128;
        int row = 16 * mw + (f >> 5), p4 = (f & 31) * 2;
        uint32_t h0, l0, h1, l1;
        split2(pfx[k].x, pfx[k].y, h0, l0); split2(pfx[k].z, pfx[k].w, h1, l1);
        smu[XH + row * 68 + p4] = h0; smu[XH + row * 68 + p4 + 1] = h1;
        smu[XL + row * 68 + p4] = l0; smu[XL + row * 68 + p4 + 1] = l1;
      }
    }
    barg(bid);   // D: group's hn + next-X visible

    // ---- stage 3 (n-warps 0,1) in parallel with next-h store (n-warps 2,3);
    //      no trailing barrier: next iteration's A/B barriers provide ordering.
    //      h-stores by ALL warps happen here (nw<2 store after fc2). ----
    if (nw < 2) {
      float acc3[4] = {0.f, 0.f, 0.f, 0.f};
      #pragma unroll
      for (int kc = 0; kc < 4; ++kc) {
        uint32_t boff = (uint32_t)(8 * nw + l7) * 36 + kc * 8 + l8b * 4;
        uint32_t bh0, bh1, bl0, bl1;
        ldsm2(bh0, bh1, sb + 4 * (W2H + boff));
        ldsm2(bl0, bl1, sb + 4 * (W2L + boff));
        uint32_t aoff = (uint32_t)(16 * mw + l15) * 36 + kc * 8 + lhalf * 4;
        uint32_t ah[4], al[4];
        ldsm4(ah, sb + 4 * (HNH + aoff));
        ldsm4(al, sb + 4 * (HNL + aoff));
        mma16816(acc3, ah, bh0, bh1);
        mma16816(acc3, al, bh0, bh1);
        mma16816(acc3, ah, bl0, bl1);
      }
      int colb = 8 * nw + 2 * cq;
      float bq0 = smf[B2O + colb], bq1 = smf[B2O + colb + 1];
      #pragma unroll
      for (int sr = 0; sr < 2; ++sr) {
        int row = 16 * mw + g + 8 * sr;
        float q0 = acc3[2 * sr] + bq0;
        float q1 = acc3[2 * sr + 1] + bq1;
        *(float2*)(out_q + ((size_t)(b0 + row) * 8 + a) * 16 + colb) = make_float2(q0, q1);
      }
    }
    if (have_next) {
      #pragma unroll
      for (int k = 0; k < 2; ++k) {
        int f = gl + k * 128;
        int row = 16 * mw + (f >> 4), p4 = (f & 15) * 2;
        uint32_t h0, l0, h1, l1;
        split2(pfh[k].x, pfh[k].y, h0, l0); split2(pfh[k].z, pfh[k].w, h1, l1);
        smu[HHq + row * 36 + p4] = h0; smu[HHq + row * 36 + p4 + 1] = h1;
        smu[HLq + row * 36 + p4] = l0; smu[HLq + row * 36 + p4 + 1] = l1;
      }
    }
  }
}

extern "C" void kernel_launch(void* const* d_in, const int* in_sizes, int n_in,
                              void* d_out, int out_size) {
  (void)n_in; (void)out_size;
  const float* inputs = (const float*)d_in[0];
  const float* hidden = (const float*)d_in[1];
  const float* W1  = (const float*)d_in[2];
  const float* b1  = (const float*)d_in[3];
  const float* Wih = (const float*)d_in[4];
  const float* bih = (const float*)d_in[5];
  const float* Whh = (const float*)d_in[6];
  const float* bhh = (const float*)d_in[7];
  const float* W2  = (const float*)d_in[8];
  const float* b2  = (const float*)d_in[9];

  const int B = in_sizes[0] / (8 * 128);   // 16384
  float* out_q = (float*)d_out;
  float* out_h = out_q + (size_t)B * 8 * 16;

  const size_t smem = (size_t)SMEM_WORDS * 4;   // 223104 B
  cudaFuncSetAttribute(rnn_v14_kernel,
                       cudaFuncAttributeMaxDynamicSharedMemorySize, (int)smem);
  dim3 grid(18, 8, 1);                          // 144 CTAs, strided tiles
  rnn_v14_kernel<<<grid, NT, smem>>>(inputs, hidden, W1, b1, Wih, bih,
                                     Whh, bhh, W2, b2, out_q, out_h);
}

// round 15
// speedup vs baseline: 1.0961x; 1.0398x over previous
#include <cuda_runtime.h>
#include <cuda_bf16.h>
#include <cstdint>
#include <cstddef>

#define DEV __device__ __forceinline__

constexpr int NT = 512;   // 16 warps: 4 m-groups x 4 n-warps
constexpr int BB = 64;    // batch rows per tile
constexpr int TOTAL_TILES = 256;   // 16384 / 64

// ---- smem layout in 32-bit words ----
// Per-tile tensors are row-partitioned by m-group (rows 16*mw..16*mw+15);
// aliased regions share the SAME row stride so group rows stay disjoint.
constexpr int B1O = 0, BRO = 64, BZO = 128, BINO = 192, BHNO = 256, B2O = 320;
constexpr int W1H = 352;               // [64][68]
constexpr int W1L = W1H + 4352;
constexpr int WIHH = W1L + 4352;       // [192][36]
constexpr int WIHL = WIHH + 6912;
constexpr int WHH_H = WIHL + 6912;
constexpr int WHH_L = WHH_H + 6912;
constexpr int W2H = WHH_L + 6912;      // [16][36]
constexpr int W2L = W2H + 576;
constexpr int XH  = W2L + 576;         // X hi [64][68]; z1 hi aliases rows (stride 68)
constexpr int XL  = XH + 4352;         // X lo [64][68]; z1 lo aliases rows (stride 68)
constexpr int HNH = XL + 4352;         // h_new hi [64][36]
constexpr int HNL = HNH + 2304;
constexpr int HHq = HNL + 2304;        // h_in hi [64][36]
constexpr int HLq = HHq + 2304;
constexpr int SMEM_WORDS = HLq + 2304; // 55776 words = 223104 B

DEV void split2(float x, float y, uint32_t& hi, uint32_t& lo) {
  __nv_bfloat16 xh = __float2bfloat16(x), yh = __float2bfloat16(y);
  __nv_bfloat16 xl = __float2bfloat16(x - __bfloat162float(xh));
  __nv_bfloat16 yl = __float2bfloat16(y - __bfloat162float(yh));
  hi = (uint32_t)__bfloat16_as_ushort(xh) | ((uint32_t)__bfloat16_as_ushort(yh) << 16);
  lo = (uint32_t)__bfloat16_as_ushort(xl) | ((uint32_t)__bfloat16_as_ushort(yl) << 16);
}
DEV float bfbits2f(uint32_t b) { return __uint_as_float(b << 16); }
DEV float tanhap(float x) {
  float y;
  asm("tanh.approx.f32 %0, %1;" : "=f"(y) : "f"(x));
  return y;
}
DEV float sigm(float x) { return fmaf(tanhap(0.5f * x), 0.5f, 0.5f); }
DEV float tanh_(float x) { return tanhap(x); }

DEV uint32_t smem_u32(const void* p) {
  uint32_t r;
  asm("{ .reg .u64 t; cvta.to.shared.u64 t, %1; cvt.u32.u64 %0, t; }" : "=r"(r) : "l"(p));
  return r;
}
DEV void barg(int id) {   // group barrier: 4 warps = 128 threads
  asm volatile("bar.sync %0, 128;" :: "r"(id) : "memory");
}
DEV void mma16816(float* c, const uint32_t* a, uint32_t b0, uint32_t b1) {
  asm volatile(
      "mma.sync.aligned.m16n8k16.row.col.f32.bf16.bf16.f32 "
      "{%0,%1,%2,%3}, {%4,%5,%6,%7}, {%8,%9}, {%0,%1,%2,%3};"
      : "+f"(c[0]), "+f"(c[1]), "+f"(c[2]), "+f"(c[3])
      : "r"(a[0]), "r"(a[1]), "r"(a[2]), "r"(a[3]), "r"(b0), "r"(b1));
}
DEV void ldsm4(uint32_t* r, uint32_t addr) {
  asm volatile("ldmatrix.sync.aligned.m8n8.x4.shared.b16 {%0,%1,%2,%3}, [%4];"
               : "=r"(r[0]), "=r"(r[1]), "=r"(r[2]), "=r"(r[3]) : "r"(addr));
}
DEV void ldsm2(uint32_t& r0, uint32_t& r1, uint32_t addr) {
  asm volatile("ldmatrix.sync.aligned.m8n8.x2.shared.b16 {%0,%1}, [%2];"
               : "=r"(r0), "=r"(r1) : "r"(addr));
}

__global__ void __launch_bounds__(NT, 1)
rnn_v15_kernel(const float* __restrict__ inputs, const float* __restrict__ hidden,
               const float* __restrict__ W1, const float* __restrict__ b1g,
               const float* __restrict__ Wih, const float* __restrict__ bihg,
               const float* __restrict__ Whh, const float* __restrict__ bhhg,
               const float* __restrict__ W2, const float* __restrict__ b2g,
               float* __restrict__ out_q, float* __restrict__ out_h)
{
  extern __shared__ uint32_t smu[];
  float* smf = (float*)smu;
  const uint32_t sb = smem_u32(smu);
  const int a = blockIdx.y;
  const int tid = threadIdx.x;
  const int w = tid >> 5, lane = tid & 31;
  const int mw = w >> 2, nw = w & 3;          // group = mw (warps 4mw..4mw+3)
  const int g = lane >> 2, cq = lane & 3;
  const int l15 = lane & 15, lhalf = lane >> 4;
  const int l7 = lane & 7, l8b = (lane >> 3) & 1;
  const int bid = mw + 1;                     // named barrier id per group
  const int gl = nw * 32 + lane;              // 0..127 within group
  const int gl2 = (nw & 1) * 32 + lane;       // 0..63 within warp-pair

  // ================= one-time: biases + weights -> bf16 hi/lo =================
  if (tid < 64) {
    smf[B1O + tid]  = b1g[a * 64 + tid];
    smf[BRO + tid]  = bihg[a * 192 + tid]       + bhhg[a * 192 + tid];
    smf[BZO + tid]  = bihg[a * 192 + 64 + tid]  + bhhg[a * 192 + 64 + tid];
    smf[BINO + tid] = bihg[a * 192 + 128 + tid];
    smf[BHNO + tid] = bhhg[a * 192 + 128 + tid];
  } else if (tid < 80) {
    smf[B2O + tid - 64] = b2g[a * 16 + tid - 64];
  }
  {
    const float* w1g = W1 + (size_t)a * 64 * 128;
    #pragma unroll 2
    for (int f = tid; f < 2048; f += NT) {            // W1 [64][128]
      int n = f >> 5, p4 = (f & 31) * 2;
      float4 v = *(const float4*)(w1g + (size_t)n * 128 + p4 * 2);
      uint32_t h0, l0, h1, l1;
      split2(v.x, v.y, h0, l0); split2(v.z, v.w, h1, l1);
      smu[W1H + n * 68 + p4] = h0; smu[W1H + n * 68 + p4 + 1] = h1;
      smu[W1L + n * 68 + p4] = l0; smu[W1L + n * 68 + p4 + 1] = l1;
    }
    const float* wig = Wih + (size_t)a * 192 * 64;
    #pragma unroll 2
    for (int f = tid; f < 3072; f += NT) {            // Wih [192][64]
      int n = f >> 4, p4 = (f & 15) * 2;
      float4 v = *(const float4*)(wig + (size_t)n * 64 + p4 * 2);
      uint32_t h0, l0, h1, l1;
      split2(v.x, v.y, h0, l0); split2(v.z, v.w, h1, l1);
      smu[WIHH + n * 36 + p4] = h0; smu[WIHH + n * 36 + p4 + 1] = h1;
      smu[WIHL + n * 36 + p4] = l0; smu[WIHL + n * 36 + p4 + 1] = l1;
    }
    const float* whg = Whh + (size_t)a * 192 * 64;
    #pragma unroll 2
    for (int f = tid; f < 3072; f += NT) {            // Whh [192][64]
      int n = f >> 4, p4 = (f & 15) * 2;
      float4 v = *(const float4*)(whg + (size_t)n * 64 + p4 * 2);
      uint32_t h0, l0, h1, l1;
      split2(v.x, v.y, h0, l0); split2(v.z, v.w, h1, l1);
      smu[WHH_H + n * 36 + p4] = h0; smu[WHH_H + n * 36 + p4 + 1] = h1;
      smu[WHH_L + n * 36 + p4] = l0; smu[WHH_L + n * 36 + p4 + 1] = l1;
    }
    const float* w2g = W2 + (size_t)a * 16 * 64;
    for (int f = tid; f < 256; f += NT) {             // W2 [16][64]
      int n = f >> 4, p4 = (f & 15) * 2;
      float4 v = *(const float4*)(w2g + (size_t)n * 64 + p4 * 2);
      uint32_t h0, l0, h1, l1;
      split2(v.x, v.y, h0, l0); split2(v.z, v.w, h1, l1);
      smu[W2H + n * 36 + p4] = h0; smu[W2H + n * 36 + p4 + 1] = h1;
      smu[W2L + n * 36 + p4] = l0; smu[W2L + n * 36 + p4 + 1] = l1;
    }
  }

  // ================= prologue: load first tile's X, h =================
  {
    const int b0 = blockIdx.x * BB;
    const float* xg = inputs + ((size_t)b0 * 8 + a) * 128;
    #pragma unroll 4
    for (int f = tid; f < 2048; f += NT) {            // X [64][128]
      int row = f >> 5, p4 = (f & 31) * 2;
      float4 v = *(const float4*)(xg + (size_t)row * 1024 + p4 * 2);
      uint32_t h0, l0, h1, l1;
      split2(v.x, v.y, h0, l0); split2(v.z, v.w, h1, l1);
      smu[XH + row * 68 + p4] = h0; smu[XH + row * 68 + p4 + 1] = h1;
      smu[XL + row * 68 + p4] = l0; smu[XL + row * 68 + p4 + 1] = l1;
    }
    const float* hg = hidden + ((size_t)b0 * 8 + a) * 64;
    #pragma unroll 2
    for (int f = tid; f < 1024; f += NT) {            // h [64][64]
      int row = f >> 4, p4 = (f & 15) * 2;
      float4 v = *(const float4*)(hg + (size_t)row * 512 + p4 * 2);
      uint32_t h0, l0, h1, l1;
      split2(v.x, v.y, h0, l0); split2(v.z, v.w, h1, l1);
      smu[HHq + row * 36 + p4] = h0; smu[HHq + row * 36 + p4 + 1] = h1;
      smu[HLq + row * 36 + p4] = l0; smu[HLq + row * 36 + p4 + 1] = l1;
    }
  }
  __syncthreads();

  // ================= pipelined tile loop (group-scoped barriers) =================
  const int G = gridDim.x;

  for (int t = blockIdx.x; t < TOTAL_TILES; t += G) {
    const int b0 = t * BB;
    const int tn = t + G;
    const bool have_next = tn < TOTAL_TILES;
    const int bn = tn * BB;

    // ---- prefetch next tile's X / h at LOOP TOP (max LDG latency cover) ----
    float4 pfx[4], pfh[4];
    if (have_next) {
      const float* xg = inputs + ((size_t)bn * 8 + a) * 128;
      #pragma unroll
      for (int k = 0; k < 4; ++k) {
        int f = gl + k * 128;                 // 0..511 within group
        int row = 16 * mw + (f >> 5), p4 = (f & 31) * 2;
        pfx[k] = *(const float4*)(xg + (size_t)row * 1024 + p4 * 2);
      }
      if (nw >= 2) {
        const float* hg = hidden + ((size_t)bn * 8 + a) * 64;
        #pragma unroll
        for (int k = 0; k < 4; ++k) {
          int f = gl2 + k * 64;               // 0..255 within group
          int row = 16 * mw + (f >> 4), p4 = (f & 15) * 2;
          pfh[k] = *(const float4*)(hg + (size_t)row * 512 + p4 * 2);
        }
      }
    }

    // ---- stage 1: z1 = relu(X @ W1^T + b1); warp covers n-tiles nw, nw+4 ----
    float acc1[2][4];
    #pragma unroll
    for (int s = 0; s < 2; ++s)
      #pragma unroll
      for (int e = 0; e < 4; ++e) acc1[s][e] = 0.f;

    #pragma unroll
    for (int kc = 0; kc < 8; ++kc) {
      uint32_t ah[4], al[4];
      uint32_t aoff = (uint32_t)(16 * mw + l15) * 68 + kc * 8 + lhalf * 4;
      ldsm4(ah, sb + 4 * (XH + aoff));
      ldsm4(al, sb + 4 * (XL + aoff));
      #pragma unroll
      for (int s = 0; s < 2; ++s) {
        uint32_t boff = (uint32_t)(8 * (nw + 4 * s) + l7) * 68 + kc * 8 + l8b * 4;
        uint32_t bh0, bh1, bl0, bl1;
        ldsm2(bh0, bh1, sb + 4 * (W1H + boff));
        ldsm2(bl0, bl1, sb + 4 * (W1L + boff));
        mma16816(acc1[s], ah, bh0, bh1);
        mma16816(acc1[s], al, bh0, bh1);
        mma16816(acc1[s], ah, bl0, bl1);
      }
    }
    barg(bid);   // A: group's X reads done (z1 overwrites this group's X rows)

    // ---- epilogue 1: bias+relu -> z1 hi/lo (row-consistent alias: stride 68) ----
    #pragma unroll
    for (int s = 0; s < 2; ++s) {
      int ntile = nw + 4 * s;
      int col = 8 * ntile + 2 * cq;
      int pidx = 4 * ntile + cq;              // z1 col word 0..31
      float bx = smf[B1O + col], by = smf[B1O + col + 1];
      #pragma unroll
      for (int sr = 0; sr < 2; ++sr) {
        int row = 16 * mw + g + 8 * sr;
        float v0 = fmaxf(acc1[s][2 * sr] + bx, 0.f);
        float v1 = fmaxf(acc1[s][2 * sr + 1] + by, 0.f);
        uint32_t ph, pl;
        split2(v0, v1, ph, pl);
        smu[XH + row * 68 + pidx] = ph;       // z1 hi lives in X-hi row (words 0..31)
        smu[XL + row * 68 + pidx] = pl;       // z1 lo lives in X-lo row
      }
    }
    barg(bid);   // B: group's z1 visible

    // ---- stage 2: gate GEMMs. N-space 256 = [r|z|i_n|h_n]; warp owns ntile = nw + 4j ----
    float acc2[8][4];
    #pragma unroll
    for (int j = 0; j < 8; ++j)
      #pragma unroll
      for (int e = 0; e < 4; ++e) acc2[j][e] = 0.f;

    #pragma unroll
    for (int kc = 0; kc < 4; ++kc) {
      uint32_t zh[4], zl[4], hh_[4], hl_[4];
      uint32_t zoff = (uint32_t)(16 * mw + l15) * 68 + kc * 8 + lhalf * 4;  // z1: stride 68
      uint32_t aoff = (uint32_t)(16 * mw + l15) * 36 + kc * 8 + lhalf * 4;  // h: stride 36
      ldsm4(zh, sb + 4 * (XH + zoff));
      ldsm4(zl, sb + 4 * (XL + zoff));
      ldsm4(hh_, sb + 4 * (HHq + aoff));
      ldsm4(hl_, sb + 4 * (HLq + aoff));
      uint32_t bbase = (uint32_t)l7 * 36 + kc * 8 + l8b * 4;
      #pragma unroll
      for (int j = 0; j < 8; ++j) {
        int ntile = nw + 4 * j;
        if (ntile < 24) {                   // z1 @ Wih rows 8*ntile  (r, z, i_n)
          uint32_t bh0, bh1, bl0, bl1;
          uint32_t o = (uint32_t)(8 * ntile) * 36 + bbase;
          ldsm2(bh0, bh1, sb + 4 * (WIHH + o));
          ldsm2(bl0, bl1, sb + 4 * (WIHL + o));
          mma16816(acc2[j], zh, bh0, bh1);
          mma16816(acc2[j], zl, bh0, bh1);
          mma16816(acc2[j], zh, bl0, bl1);
        }
        if (ntile < 16 || ntile >= 24) {    // h @ Whh (r, z rows; h_n rows-64)
          int n0 = (ntile < 16) ? 8 * ntile : 8 * ntile - 64;
          uint32_t bh0, bh1, bl0, bl1;
          uint32_t o = (uint32_t)n0 * 36 + bbase;
          ldsm2(bh0, bh1, sb + 4 * (WHH_H + o));
          ldsm2(bl0, bl1, sb + 4 * (WHH_L + o));
          mma16816(acc2[j], hh_, bh0, bh1);
          mma16816(acc2[j], hl_, bh0, bh1);
          mma16816(acc2[j], hh_, bl0, bl1);
        }
      }
    }
    barg(bid);   // C: group's z1 / h reads done

    // ---- epilogue 2: GRU -> h_new (+gmem); store next X (group rows) ----
    #pragma unroll
    for (int s = 0; s < 2; ++s) {
      int ntile = nw + 4 * s;
      int cb = 8 * ntile + 2 * cq;
      int pidx = 4 * ntile + cq;
      float brv0 = smf[BRO + cb],  brv1 = smf[BRO + cb + 1];
      float bzv0 = smf[BZO + cb],  bzv1 = smf[BZO + cb + 1];
      float biv0 = smf[BINO + cb], biv1 = smf[BINO + cb + 1];
      float bnv0 = smf[BHNO + cb], bnv1 = smf[BHNO + cb + 1];
      #pragma unroll
      for (int sr = 0; sr < 2; ++sr) {
        int row = 16 * mw + g + 8 * sr;
        uint32_t uh = smu[HHq + row * 36 + pidx], ul = smu[HLq + row * 36 + pidx];
        float ho0 = bfbits2f(uh & 0xffffu) + bfbits2f(ul & 0xffffu);
        float ho1 = bfbits2f(uh >> 16) + bfbits2f(ul >> 16);
        float rv0 = sigm(acc2[s][2 * sr] + brv0);
        float rv1 = sigm(acc2[s][2 * sr + 1] + brv1);
        float zv0 = sigm(acc2[2 + s][2 * sr] + bzv0);
        float zv1 = sigm(acc2[2 + s][2 * sr + 1] + bzv1);
        float nv0 = tanh_(acc2[4 + s][2 * sr] + biv0 +
                          rv0 * (acc2[6 + s][2 * sr] + bnv0));
        float nv1 = tanh_(acc2[4 + s][2 * sr + 1] + biv1 +
                          rv1 * (acc2[6 + s][2 * sr + 1] + bnv1));
        float hn0 = nv0 + zv0 * (ho0 - nv0);
        float hn1 = nv1 + zv1 * (ho1 - nv1);
        uint32_t ph, pl;
        split2(hn0, hn1, ph, pl);
        smu[HNH + row * 36 + pidx] = ph;
        smu[HNL + row * 36 + pidx] = pl;
        *(float2*)(out_h + ((size_t)(b0 + row) * 8 + a) * 64 + cb) = make_float2(hn0, hn1);
      }
    }
    if (have_next) {
      #pragma unroll
      for (int k = 0; k < 4; ++k) {
        int f = gl + k * 128;
        int row = 16 * mw + (f >> 5), p4 = (f & 31) * 2;
        uint32_t h0, l0, h1, l1;
        split2(pfx[k].x, pfx[k].y, h0, l0); split2(pfx[k].z, pfx[k].w, h1, l1);
        smu[XH + row * 68 + p4] = h0; smu[XH + row * 68 + p4 + 1] = h1;
        smu[XL + row * 68 + p4] = l0; smu[XL + row * 68 + p4 + 1] = l1;
      }
    }
    barg(bid);   // D: group's hn + next-X visible

    // ---- stage 3 (n-warps 0,1) in parallel with next-h store (n-warps 2,3);
    //      no trailing barrier: next iteration's A/B barriers provide ordering ----
    if (nw < 2) {
      float acc3[4] = {0.f, 0.f, 0.f, 0.f};
      #pragma unroll
      for (int kc = 0; kc < 4; ++kc) {
        uint32_t boff = (uint32_t)(8 * nw + l7) * 36 + kc * 8 + l8b * 4;
        uint32_t bh0, bh1, bl0, bl1;
        ldsm2(bh0, bh1, sb + 4 * (W2H + boff));
        ldsm2(bl0, bl1, sb + 4 * (W2L + boff));
        uint32_t aoff = (uint32_t)(16 * mw + l15) * 36 + kc * 8 + lhalf * 4;
        uint32_t ah[4], al[4];
        ldsm4(ah, sb + 4 * (HNH + aoff));
        ldsm4(al, sb + 4 * (HNL + aoff));
        mma16816(acc3, ah, bh0, bh1);
        mma16816(acc3, al, bh0, bh1);
        mma16816(acc3, ah, bl0, bl1);
      }
      int colb = 8 * nw + 2 * cq;
      float bq0 = smf[B2O + colb], bq1 = smf[B2O + colb + 1];
      #pragma unroll
      for (int sr = 0; sr < 2; ++sr) {
        int row = 16 * mw + g + 8 * sr;
        float q0 = acc3[2 * sr] + bq0;
        float q1 = acc3[2 * sr + 1] + bq1;
        *(float2*)(out_q + ((size_t)(b0 + row) * 8 + a) * 16 + colb) = make_float2(q0, q1);
      }
    } else if (have_next) {
      #pragma unroll
      for (int k = 0; k < 4; ++k) {
        int f = gl2 + k * 64;
        int row = 16 * mw + (f >> 4), p4 = (f & 15) * 2;
        uint32_t h0, l0, h1, l1;
        split2(pfh[k].x, pfh[k].y, h0, l0); split2(pfh[k].z, pfh[k].w, h1, l1);
        smu[HHq + row * 36 + p4] = h0; smu[HHq + row * 36 + p4 + 1] = h1;
        smu[HLq + row * 36 + p4] = l0; smu[HLq + row * 36 + p4 + 1] = l1;
      }
    }
  }
}

extern "C" void kernel_launch(void* const* d_in, const int* in_sizes, int n_in,
                              void* d_out, int out_size) {
  (void)n_in; (void)out_size;
  const float* inputs = (const float*)d_in[0];
  const float* hidden = (const float*)d_in[1];
  const float* W1  = (const float*)d_in[2];
  const float* b1  = (const float*)d_in[3];
  const float* Wih = (const float*)d_in[4];
  const float* bih = (const float*)d_in[5];
  const float* Whh = (const float*)d_in[6];
  const float* bhh = (const float*)d_in[7];
  const float* W2  = (const float*)d_in[8];
  const float* b2  = (const float*)d_in[9];

  const int B = in_sizes[0] / (8 * 128);   // 16384
  float* out_q = (float*)d_out;
  float* out_h = out_q + (size_t)B * 8 * 16;

  const size_t smem = (size_t)SMEM_WORDS * 4;   // 223104 B
  cudaFuncSetAttribute(rnn_v15_kernel,
                       cudaFuncAttributeMaxDynamicSharedMemorySize, (int)smem);
  dim3 grid(18, 8, 1);                          // 144 CTAs, strided tiles
  rnn_v15_kernel<<<grid, NT, smem>>>(inputs, hidden, W1, b1, Wih, bih,
                                     Whh, bhh, W2, b2, out_q, out_h);
}

// round 16
// speedup vs baseline: 1.1012x; 1.0046x over previous
#include <cuda_runtime.h>
#include <cuda_bf16.h>
#include <cstdint>
#include <cstddef>

#define DEV __device__ __forceinline__

constexpr int NT = 512;   // 16 warps: 4 m-groups x 4 n-warps
constexpr int BB = 64;    // batch rows per tile
constexpr int TOTAL_TILES = 256;   // 16384 / 64

// ---- smem layout in 32-bit words ----
constexpr int B1O = 0, BRO = 64, BZO = 128, BINO = 192, BHNO = 256, B2O = 320;
constexpr int W1H = 352;               // [64][68]
constexpr int W1L = W1H + 4352;
constexpr int WIHH = W1L + 4352;       // [192][36]
constexpr int WIHL = WIHH + 6912;
constexpr int WHH_H = WIHL + 6912;
constexpr int WHH_L = WHH_H + 6912;
constexpr int W2H = WHH_L + 6912;      // [16][36]
constexpr int W2L = W2H + 576;
constexpr int XH  = W2L + 576;         // X hi [64][68]; z1 hi aliases rows (stride 68)
constexpr int XL  = XH + 4352;         // X lo [64][68]; z1 lo aliases rows (stride 68)
constexpr int HNH = XL + 4352;         // h_new hi [64][36]
constexpr int HNL = HNH + 2304;
constexpr int HHq = HNL + 2304;        // h_in hi [64][36]
constexpr int HLq = HHq + 2304;
constexpr int SMEM_WORDS = HLq + 2304; // 55776 words = 223104 B

DEV void split2(float x, float y, uint32_t& hi, uint32_t& lo) {
  __nv_bfloat16 xh = __float2bfloat16(x), yh = __float2bfloat16(y);
  __nv_bfloat16 xl = __float2bfloat16(x - __bfloat162float(xh));
  __nv_bfloat16 yl = __float2bfloat16(y - __bfloat162float(yh));
  hi = (uint32_t)__bfloat16_as_ushort(xh) | ((uint32_t)__bfloat16_as_ushort(yh) << 16);
  lo = (uint32_t)__bfloat16_as_ushort(xl) | ((uint32_t)__bfloat16_as_ushort(yl) << 16);
}
DEV float bfbits2f(uint32_t b) { return __uint_as_float(b << 16); }
DEV float tanhap(float x) {
  float y;
  asm("tanh.approx.f32 %0, %1;" : "=f"(y) : "f"(x));
  return y;
}
DEV float sigm(float x) { return fmaf(tanhap(0.5f * x), 0.5f, 0.5f); }
DEV float tanh_(float x) { return tanhap(x); }

DEV uint32_t smem_u32(const void* p) {
  uint32_t r;
  asm("{ .reg .u64 t; cvta.to.shared.u64 t, %1; cvt.u32.u64 %0, t; }" : "=r"(r) : "l"(p));
  return r;
}
DEV void barg(int id) {   // group barrier: 4 warps = 128 threads
  asm volatile("bar.sync %0, 128;" :: "r"(id) : "memory");
}
DEV void mma16816(float* c, const uint32_t* a, uint32_t b0, uint32_t b1) {
  asm volatile(
      "mma.sync.aligned.m16n8k16.row.col.f32.bf16.bf16.f32 "
      "{%0,%1,%2,%3}, {%4,%5,%6,%7}, {%8,%9}, {%0,%1,%2,%3};"
      : "+f"(c[0]), "+f"(c[1]), "+f"(c[2]), "+f"(c[3])
      : "r"(a[0]), "r"(a[1]), "r"(a[2]), "r"(a[3]), "r"(b0), "r"(b1));
}
DEV void ldsm4(uint32_t* r, uint32_t addr) {
  asm volatile("ldmatrix.sync.aligned.m8n8.x4.shared.b16 {%0,%1,%2,%3}, [%4];"
               : "=r"(r[0]), "=r"(r[1]), "=r"(r[2]), "=r"(r[3]) : "r"(addr));
}
DEV void ldsm2(uint32_t& r0, uint32_t& r1, uint32_t addr) {
  asm volatile("ldmatrix.sync.aligned.m8n8.x2.shared.b16 {%0,%1}, [%2];"
               : "=r"(r0), "=r"(r1) : "r"(addr));
}

__global__ void __launch_bounds__(NT, 1)
rnn_v16_kernel(const float* __restrict__ inputs, const float* __restrict__ hidden,
               const float* __restrict__ W1, const float* __restrict__ b1g,
               const float* __restrict__ Wih, const float* __restrict__ bihg,
               const float* __restrict__ Whh, const float* __restrict__ bhhg,
               const float* __restrict__ W2, const float* __restrict__ b2g,
               float* __restrict__ out_q, float* __restrict__ out_h)
{
  extern __shared__ uint32_t smu[];
  float* smf = (float*)smu;
  const uint32_t sb = smem_u32(smu);
  const int a = blockIdx.y;
  const int tid = threadIdx.x;
  const int w = tid >> 5, lane = tid & 31;
  const int mw = w >> 2, nw = w & 3;          // group = mw (warps 4mw..4mw+3)
  const int g = lane >> 2, cq = lane & 3;
  const int l15 = lane & 15, lhalf = lane >> 4;
  const int l7 = lane & 7, l8b = (lane >> 3) & 1;
  const int bid = mw + 1;                     // named barrier id per group
  const int gl = nw * 32 + lane;              // 0..127 within group
  const int gl2 = (nw & 1) * 32 + lane;       // 0..63 within warp-pair

  // ================= one-time: biases + weights -> bf16 hi/lo =================
  if (tid < 64) {
    smf[B1O + tid]  = b1g[a * 64 + tid];
    smf[BRO + tid]  = bihg[a * 192 + tid]       + bhhg[a * 192 + tid];
    smf[BZO + tid]  = bihg[a * 192 + 64 + tid]  + bhhg[a * 192 + 64 + tid];
    smf[BINO + tid] = bihg[a * 192 + 128 + tid];
    smf[BHNO + tid] = bhhg[a * 192 + 128 + tid];
  } else if (tid < 80) {
    smf[B2O + tid - 64] = b2g[a * 16 + tid - 64];
  }
  {
    const float* w1g = W1 + (size_t)a * 64 * 128;
    #pragma unroll 2
    for (int f = tid; f < 2048; f += NT) {            // W1 [64][128]
      int n = f >> 5, p4 = (f & 31) * 2;
      float4 v = *(const float4*)(w1g + (size_t)n * 128 + p4 * 2);
      uint32_t h0, l0, h1, l1;
      split2(v.x, v.y, h0, l0); split2(v.z, v.w, h1, l1);
      smu[W1H + n * 68 + p4] = h0; smu[W1H + n * 68 + p4 + 1] = h1;
      smu[W1L + n * 68 + p4] = l0; smu[W1L + n * 68 + p4 + 1] = l1;
    }
    const float* wig = Wih + (size_t)a * 192 * 64;
    #pragma unroll 2
    for (int f = tid; f < 3072; f += NT) {            // Wih [192][64]
      int n = f >> 4, p4 = (f & 15) * 2;
      float4 v = *(const float4*)(wig + (size_t)n * 64 + p4 * 2);
      uint32_t h0, l0, h1, l1;
      split2(v.x, v.y, h0, l0); split2(v.z, v.w, h1, l1);
      smu[WIHH + n * 36 + p4] = h0; smu[WIHH + n * 36 + p4 + 1] = h1;
      smu[WIHL + n * 36 + p4] = l0; smu[WIHL + n * 36 + p4 + 1] = l1;
    }
    const float* whg = Whh + (size_t)a * 192 * 64;
    #pragma unroll 2
    for (int f = tid; f < 3072; f += NT) {            // Whh [192][64]
      int n = f >> 4, p4 = (f & 15) * 2;
      float4 v = *(const float4*)(whg + (size_t)n * 64 + p4 * 2);
      uint32_t h0, l0, h1, l1;
      split2(v.x, v.y, h0, l0); split2(v.z, v.w, h1, l1);
      smu[WHH_H + n * 36 + p4] = h0; smu[WHH_H + n * 36 + p4 + 1] = h1;
      smu[WHH_L + n * 36 + p4] = l0; smu[WHH_L + n * 36 + p4 + 1] = l1;
    }
    const float* w2g = W2 + (size_t)a * 16 * 64;
    for (int f = tid; f < 256; f += NT) {             // W2 [16][64]
      int n = f >> 4, p4 = (f & 15) * 2;
      float4 v = *(const float4*)(w2g + (size_t)n * 64 + p4 * 2);
      uint32_t h0, l0, h1, l1;
      split2(v.x, v.y, h0, l0); split2(v.z, v.w, h1, l1);
      smu[W2H + n * 36 + p4] = h0; smu[W2H + n * 36 + p4 + 1] = h1;
      smu[W2L + n * 36 + p4] = l0; smu[W2L + n * 36 + p4 + 1] = l1;
    }
  }

  // ================= prologue: load first tile's X, h =================
  {
    const int b0 = blockIdx.x * BB;
    const float* xg = inputs + ((size_t)b0 * 8 + a) * 128;
    #pragma unroll 4
    for (int f = tid; f < 2048; f += NT) {            // X [64][128]
      int row = f >> 5, p4 = (f & 31) * 2;
      float4 v = *(const float4*)(xg + (size_t)row * 1024 + p4 * 2);
      uint32_t h0, l0, h1, l1;
      split2(v.x, v.y, h0, l0); split2(v.z, v.w, h1, l1);
      smu[XH + row * 68 + p4] = h0; smu[XH + row * 68 + p4 + 1] = h1;
      smu[XL + row * 68 + p4] = l0; smu[XL + row * 68 + p4 + 1] = l1;
    }
    const float* hg = hidden + ((size_t)b0 * 8 + a) * 64;
    #pragma unroll 2
    for (int f = tid; f < 1024; f += NT) {            // h [64][64]
      int row = f >> 4, p4 = (f & 15) * 2;
      float4 v = *(const float4*)(hg + (size_t)row * 512 + p4 * 2);
      uint32_t h0, l0, h1, l1;
      split2(v.x, v.y, h0, l0); split2(v.z, v.w, h1, l1);
      smu[HHq + row * 36 + p4] = h0; smu[HHq + row * 36 + p4 + 1] = h1;
      smu[HLq + row * 36 + p4] = l0; smu[HLq + row * 36 + p4 + 1] = l1;
    }
  }
  __syncthreads();

  // ================= pipelined tile loop (group-scoped barriers) =================
  const int G = gridDim.x;

  for (int t = blockIdx.x; t < TOTAL_TILES; t += G) {
    const int b0 = t * BB;
    const int tn = t + G;
    const bool have_next = tn < TOTAL_TILES;
    const int bn = tn * BB;

    // ---- prefetch next tile's X / h at LOOP TOP (max LDG latency cover) ----
    float4 pfx[4], pfh[4];
    if (have_next) {
      const float* xg = inputs + ((size_t)bn * 8 + a) * 128;
      #pragma unroll
      for (int k = 0; k < 4; ++k) {
        int f = gl + k * 128;                 // 0..511 within group
        int row = 16 * mw + (f >> 5), p4 = (f & 31) * 2;
        pfx[k] = *(const float4*)(xg + (size_t)row * 1024 + p4 * 2);
      }
      if (nw >= 2) {
        const float* hg = hidden + ((size_t)bn * 8 + a) * 64;
        #pragma unroll
        for (int k = 0; k < 4; ++k) {
          int f = gl2 + k * 64;               // 0..255 within group
          int row = 16 * mw + (f >> 4), p4 = (f & 15) * 2;
          pfh[k] = *(const float4*)(hg + (size_t)row * 512 + p4 * 2);
        }
      }
    }

    // ---- stage 1: z1 = relu(X @ W1^T + b1); even/odd-kc accumulator split ----
    float acc1e[2][4], acc1o[2][4];
    #pragma unroll
    for (int s = 0; s < 2; ++s)
      #pragma unroll
      for (int e = 0; e < 4; ++e) { acc1e[s][e] = 0.f; acc1o[s][e] = 0.f; }

    #pragma unroll
    for (int kc = 0; kc < 8; ++kc) {
      float (*acc)[4] = (kc & 1) ? acc1o : acc1e;
      uint32_t ah[4], al[4];
      uint32_t aoff = (uint32_t)(16 * mw + l15) * 68 + kc * 8 + lhalf * 4;
      ldsm4(ah, sb + 4 * (XH + aoff));
      ldsm4(al, sb + 4 * (XL + aoff));
      #pragma unroll
      for (int s = 0; s < 2; ++s) {
        uint32_t boff = (uint32_t)(8 * (nw + 4 * s) + l7) * 68 + kc * 8 + l8b * 4;
        uint32_t bh0, bh1, bl0, bl1;
        ldsm2(bh0, bh1, sb + 4 * (W1H + boff));
        ldsm2(bl0, bl1, sb + 4 * (W1L + boff));
        mma16816(acc[s], ah, bh0, bh1);
        mma16816(acc[s], al, bh0, bh1);
        mma16816(acc[s], ah, bl0, bl1);
      }
    }
    barg(bid);   // A: group's X reads done (z1 overwrites this group's X rows)

    // ---- epilogue 1: bias+relu -> z1 hi/lo (row-consistent alias: stride 68) ----
    #pragma unroll
    for (int s = 0; s < 2; ++s) {
      int ntile = nw + 4 * s;
      int col = 8 * ntile + 2 * cq;
      int pidx = 4 * ntile + cq;              // z1 col word 0..31
      float bx = smf[B1O + col], by = smf[B1O + col + 1];
      #pragma unroll
      for (int sr = 0; sr < 2; ++sr) {
        int row = 16 * mw + g + 8 * sr;
        float v0 = fmaxf(acc1e[s][2 * sr] + acc1o[s][2 * sr] + bx, 0.f);
        float v1 = fmaxf(acc1e[s][2 * sr + 1] + acc1o[s][2 * sr + 1] + by, 0.f);
        uint32_t ph, pl;
        split2(v0, v1, ph, pl);
        smu[XH + row * 68 + pidx] = ph;
        smu[XL + row * 68 + pidx] = pl;
      }
    }
    barg(bid);   // B: group's z1 visible

    // ---- stage 2: gate GEMMs. N-space 256 = [r|z|i_n|h_n]; warp owns ntile = nw + 4j ----
    float acc2[8][4];
    #pragma unroll
    for (int j = 0; j < 8; ++j)
      #pragma unroll
      for (int e = 0; e < 4; ++e) acc2[j][e] = 0.f;

    #pragma unroll
    for (int kc = 0; kc < 4; ++kc) {
      uint32_t zh[4], zl[4], hh_[4], hl_[4];
      uint32_t zoff = (uint32_t)(16 * mw + l15) * 68 + kc * 8 + lhalf * 4;  // z1: stride 68
      uint32_t aoff = (uint32_t)(16 * mw + l15) * 36 + kc * 8 + lhalf * 4;  // h: stride 36
      ldsm4(zh, sb + 4 * (XH + zoff));
      ldsm4(zl, sb + 4 * (XL + zoff));
      ldsm4(hh_, sb + 4 * (HHq + aoff));
      ldsm4(hl_, sb + 4 * (HLq + aoff));
      uint32_t bbase = (uint32_t)l7 * 36 + kc * 8 + l8b * 4;
      #pragma unroll
      for (int j = 0; j < 8; ++j) {
        int ntile = nw + 4 * j;
        if (ntile < 24) {                   // z1 @ Wih rows 8*ntile  (r, z, i_n)
          uint32_t bh0, bh1, bl0, bl1;
          uint32_t o = (uint32_t)(8 * ntile) * 36 + bbase;
          ldsm2(bh0, bh1, sb + 4 * (WIHH + o));
          ldsm2(bl0, bl1, sb + 4 * (WIHL + o));
          mma16816(acc2[j], zh, bh0, bh1);
          mma16816(acc2[j], zl, bh0, bh1);
          mma16816(acc2[j], zh, bl0, bl1);
        }
        if (ntile < 16 || ntile >= 24) {    // h @ Whh (r, z rows; h_n rows-64)
          int n0 = (ntile < 16) ? 8 * ntile : 8 * ntile - 64;
          uint32_t bh0, bh1, bl0, bl1;
          uint32_t o = (uint32_t)n0 * 36 + bbase;
          ldsm2(bh0, bh1, sb + 4 * (WHH_H + o));
          ldsm2(bl0, bl1, sb + 4 * (WHH_L + o));
          mma16816(acc2[j], hh_, bh0, bh1);
          mma16816(acc2[j], hl_, bh0, bh1);
          mma16816(acc2[j], hh_, bl0, bl1);
        }
      }
    }
    barg(bid);   // C: group's z1 / h reads done

    // ---- epilogue 2: GRU -> h_new (+gmem); store next X (group rows) ----
    #pragma unroll
    for (int s = 0; s < 2; ++s) {
      int ntile = nw + 4 * s;
      int cb = 8 * ntile + 2 * cq;
      int pidx = 4 * ntile + cq;
      float brv0 = smf[BRO + cb],  brv1 = smf[BRO + cb + 1];
      float bzv0 = smf[BZO + cb],  bzv1 = smf[BZO + cb + 1];
      float biv0 = smf[BINO + cb], biv1 = smf[BINO + cb + 1];
      float bnv0 = smf[BHNO + cb], bnv1 = smf[BHNO + cb + 1];
      #pragma unroll
      for (int sr = 0; sr < 2; ++sr) {
        int row = 16 * mw + g + 8 * sr;
        uint32_t uh = smu[HHq + row * 36 + pidx], ul = smu[HLq + row * 36 + pidx];
        float ho0 = bfbits2f(uh & 0xffffu) + bfbits2f(ul & 0xffffu);
        float ho1 = bfbits2f(uh >> 16) + bfbits2f(ul >> 16);
        float rv0 = sigm(acc2[s][2 * sr] + brv0);
        float rv1 = sigm(acc2[s][2 * sr + 1] + brv1);
        float zv0 = sigm(acc2[2 + s][2 * sr] + bzv0);
        float zv1 = sigm(acc2[2 + s][2 * sr + 1] + bzv1);
        float nv0 = tanh_(acc2[4 + s][2 * sr] + biv0 +
                          rv0 * (acc2[6 + s][2 * sr] + bnv0));
        float nv1 = tanh_(acc2[4 + s][2 * sr + 1] + biv1 +
                          rv1 * (acc2[6 + s][2 * sr + 1] + bnv1));
        float hn0 = nv0 + zv0 * (ho0 - nv0);
        float hn1 = nv1 + zv1 * (ho1 - nv1);
        uint32_t ph, pl;
        split2(hn0, hn1, ph, pl);
        smu[HNH + row * 36 + pidx] = ph;
        smu[HNL + row * 36 + pidx] = pl;
        *(float2*)(out_h + ((size_t)(b0 + row) * 8 + a) * 64 + cb) = make_float2(hn0, hn1);
      }
    }
    if (have_next) {
      #pragma unroll
      for (int k = 0; k < 4; ++k) {
        int f = gl + k * 128;
        int row = 16 * mw + (f >> 5), p4 = (f & 31) * 2;
        uint32_t h0, l0, h1, l1;
        split2(pfx[k].x, pfx[k].y, h0, l0); split2(pfx[k].z, pfx[k].w, h1, l1);
        smu[XH + row * 68 + p4] = h0; smu[XH + row * 68 + p4 + 1] = h1;
        smu[XL + row * 68 + p4] = l0; smu[XL + row * 68 + p4 + 1] = l1;
      }
    }
    barg(bid);   // D: group's hn + next-X visible

    // ---- stage 3 (n-warps 0,1, even/odd-kc split) || next-h store (n-warps 2,3) ----
    if (nw < 2) {
      float acc3e[4] = {0.f, 0.f, 0.f, 0.f};
      float acc3o[4] = {0.f, 0.f, 0.f, 0.f};
      #pragma unroll
      for (int kc = 0; kc < 4; ++kc) {
        float* acc = (kc & 1) ? acc3o : acc3e;
        uint32_t boff = (uint32_t)(8 * nw + l7) * 36 + kc * 8 + l8b * 4;
        uint32_t bh0, bh1, bl0, bl1;
        ldsm2(bh0, bh1, sb + 4 * (W2H + boff));
        ldsm2(bl0, bl1, sb + 4 * (W2L + boff));
        uint32_t aoff = (uint32_t)(16 * mw + l15) * 36 + kc * 8 + lhalf * 4;
        uint32_t ah[4], al[4];
        ldsm4(ah, sb + 4 * (HNH + aoff));
        ldsm4(al, sb + 4 * (HNL + aoff));
        mma16816(acc, ah, bh0, bh1);
        mma16816(acc, al, bh0, bh1);
        mma16816(acc, ah, bl0, bl1);
      }
      int colb = 8 * nw + 2 * cq;
      float bq0 = smf[B2O + colb], bq1 = smf[B2O + colb + 1];
      #pragma unroll
      for (int sr = 0; sr < 2; ++sr) {
        int row = 16 * mw + g + 8 * sr;
        float q0 = acc3e[2 * sr] + acc3o[2 * sr] + bq0;
        float q1 = acc3e[2 * sr + 1] + acc3o[2 * sr + 1] + bq1;
        *(float2*)(out_q + ((size_t)(b0 + row) * 8 + a) * 16 + colb) = make_float2(q0, q1);
      }
    } else if (have_next) {
      #pragma unroll
      for (int k = 0; k < 4; ++k) {
        int f = gl2 + k * 64;
        int row = 16 * mw + (f >> 4), p4 = (f & 15) * 2;
        uint32_t h0, l0, h1, l1;
        split2(pfh[k].x, pfh[k].y, h0, l0); split2(pfh[k].z, pfh[k].w, h1, l1);
        smu[HHq + row * 36 + p4] = h0; smu[HHq + row * 36 + p4 + 1] = h1;
        smu[HLq + row * 36 + p4] = l0; smu[HLq + row * 36 + p4 + 1] = l1;
      }
    }
  }
}

extern "C" void kernel_launch(void* const* d_in, const int* in_sizes, int n_in,
                              void* d_out, int out_size) {
  (void)n_in; (void)out_size;
  const float* inputs = (const float*)d_in[0];
  const float* hidden = (const float*)d_in[1];
  const float* W1  = (const float*)d_in[2];
  const float* b1  = (const float*)d_in[3];
  const float* Wih = (const float*)d_in[4];
  const float* bih = (const float*)d_in[5];
  const float* Whh = (const float*)d_in[6];
  const float* bhh = (const float*)d_in[7];
  const float* W2  = (const float*)d_in[8];
  const float* b2  = (const float*)d_in[9];

  const int B = in_sizes[0] / (8 * 128);   // 16384
  float* out_q = (float*)d_out;
  float* out_h = out_q + (size_t)B * 8 * 16;

  const size_t smem = (size_t)SMEM_WORDS * 4;   // 223104 B
  cudaFuncSetAttribute(rnn_v16_kernel,
                       cudaFuncAttributeMaxDynamicSharedMemorySize, (int)smem);
  dim3 grid(18, 8, 1);                          // 144 CTAs, strided tiles
  rnn_v16_kernel<<<grid, NT, smem>>>(inputs, hidden, W1, b1, Wih, bih,
                                     Whh, bhh, W2, b2, out_q, out_h);
}

// round 17
// speedup vs baseline: 1.2013x; 1.0909x over previous
#include <cuda_runtime.h>
#include <cuda_bf16.h>
#include <cstdint>
#include <cstddef>

#define DEV __device__ __forceinline__

constexpr int NT = 512;   // 16 warps: 4 m-groups x 4 n-warps
constexpr int BB = 64;    // batch rows per tile
constexpr int TOTAL_TILES = 256;   // 16384 / 64

// ---- smem layout in 32-bit words ----
constexpr int B1O = 0, BRO = 64, BZO = 128, BINO = 192, BHNO = 256, B2O = 320;
constexpr int W1H = 352;               // [64][68]
constexpr int W1L = W1H + 4352;
constexpr int WIHH = W1L + 4352;       // [192][36]
constexpr int WIHL = WIHH + 6912;
constexpr int WHH_H = WIHL + 6912;
constexpr int WHH_L = WHH_H + 6912;
constexpr int W2H = WHH_L + 6912;      // [16][36]
constexpr int W2L = W2H + 576;
constexpr int XH  = W2L + 576;         // X hi [64][68]; z1 hi aliases rows (stride 68)
constexpr int XL  = XH + 4352;         // X lo [64][68]; z1 lo aliases rows (stride 68)
constexpr int HNH = XL + 4352;         // h_new hi [64][36]
constexpr int HNL = HNH + 2304;
constexpr int HHq = HNL + 2304;        // h_in hi [64][36]
constexpr int HLq = HHq + 2304;
constexpr int SMEM_WORDS = HLq + 2304; // 55776 words = 223104 B

DEV void split2(float x, float y, uint32_t& hi, uint32_t& lo) {
  __nv_bfloat16 xh = __float2bfloat16(x), yh = __float2bfloat16(y);
  __nv_bfloat16 xl = __float2bfloat16(x - __bfloat162float(xh));
  __nv_bfloat16 yl = __float2bfloat16(y - __bfloat162float(yh));
  hi = (uint32_t)__bfloat16_as_ushort(xh) | ((uint32_t)__bfloat16_as_ushort(yh) << 16);
  lo = (uint32_t)__bfloat16_as_ushort(xl) | ((uint32_t)__bfloat16_as_ushort(yl) << 16);
}
DEV float bfbits2f(uint32_t b) { return __uint_as_float(b << 16); }
DEV float tanhap(float x) {
  float y;
  asm("tanh.approx.f32 %0, %1;" : "=f"(y) : "f"(x));
  return y;
}
DEV float sigm(float x) { return fmaf(tanhap(0.5f * x), 0.5f, 0.5f); }
DEV float tanh_(float x) { return tanhap(x); }

DEV uint32_t smem_u32(const void* p) {
  uint32_t r;
  asm("{ .reg .u64 t; cvta.to.shared.u64 t, %1; cvt.u32.u64 %0, t; }" : "=r"(r) : "l"(p));
  return r;
}
DEV void barg(int id) {   // group barrier: 4 warps = 128 threads
  asm volatile("bar.sync %0, 128;" :: "r"(id) : "memory");
}
DEV void mma16816(float* c, const uint32_t* a, uint32_t b0, uint32_t b1) {
  asm volatile(
      "mma.sync.aligned.m16n8k16.row.col.f32.bf16.bf16.f32 "
      "{%0,%1,%2,%3}, {%4,%5,%6,%7}, {%8,%9}, {%0,%1,%2,%3};"
      : "+f"(c[0]), "+f"(c[1]), "+f"(c[2]), "+f"(c[3])
      : "r"(a[0]), "r"(a[1]), "r"(a[2]), "r"(a[3]), "r"(b0), "r"(b1));
}
DEV void ldsm4(uint32_t* r, uint32_t addr) {
  asm volatile("ldmatrix.sync.aligned.m8n8.x4.shared.b16 {%0,%1,%2,%3}, [%4];"
               : "=r"(r[0]), "=r"(r[1]), "=r"(r[2]), "=r"(r[3]) : "r"(addr));
}
DEV void ldsm2(uint32_t& r0, uint32_t& r1, uint32_t addr) {
  asm volatile("ldmatrix.sync.aligned.m8n8.x2.shared.b16 {%0,%1}, [%2];"
               : "=r"(r0), "=r"(r1) : "r"(addr));
}

__global__ void __launch_bounds__(NT, 1)
rnn_v17_kernel(const float* __restrict__ inputs, const float* __restrict__ hidden,
               const float* __restrict__ W1, const float* __restrict__ b1g,
               const float* __restrict__ Wih, const float* __restrict__ bihg,
               const float* __restrict__ Whh, const float* __restrict__ bhhg,
               const float* __restrict__ W2, const float* __restrict__ b2g,
               float* __restrict__ out_q, float* __restrict__ out_h)
{
  extern __shared__ uint32_t smu[];
  float* smf = (float*)smu;
  const uint32_t sb = smem_u32(smu);
  const int a = blockIdx.y;
  const int tid = threadIdx.x;
  const int w = tid >> 5, lane = tid & 31;
  const int mw = w >> 2, nw = w & 3;          // group = mw (warps 4mw..4mw+3)
  const int g = lane >> 2, cq = lane & 3;
  const int l15 = lane & 15, lhalf = lane >> 4;
  const int l7 = lane & 7, l8b = (lane >> 3) & 1;
  const int bid = mw + 1;                     // named barrier id per group
  const int gl = nw * 32 + lane;              // 0..127 within group
  const int gl2 = (nw & 1) * 32 + lane;       // 0..63 within warp-pair

  // ================= one-time: biases + weights -> bf16 hi/lo =================
  if (tid < 64) {
    smf[B1O + tid]  = b1g[a * 64 + tid];
    smf[BRO + tid]  = bihg[a * 192 + tid]       + bhhg[a * 192 + tid];
    smf[BZO + tid]  = bihg[a * 192 + 64 + tid]  + bhhg[a * 192 + 64 + tid];
    smf[BINO + tid] = bihg[a * 192 + 128 + tid];
    smf[BHNO + tid] = bhhg[a * 192 + 128 + tid];
  } else if (tid < 80) {
    smf[B2O + tid - 64] = b2g[a * 16 + tid - 64];
  }
  {
    const float* w1g = W1 + (size_t)a * 64 * 128;
    #pragma unroll 2
    for (int f = tid; f < 2048; f += NT) {            // W1 [64][128]
      int n = f >> 5, p4 = (f & 31) * 2;
      float4 v = *(const float4*)(w1g + (size_t)n * 128 + p4 * 2);
      uint32_t h0, l0, h1, l1;
      split2(v.x, v.y, h0, l0); split2(v.z, v.w, h1, l1);
      smu[W1H + n * 68 + p4] = h0; smu[W1H + n * 68 + p4 + 1] = h1;
      smu[W1L + n * 68 + p4] = l0; smu[W1L + n * 68 + p4 + 1] = l1;
    }
    const float* wig = Wih + (size_t)a * 192 * 64;
    #pragma unroll 2
    for (int f = tid; f < 3072; f += NT) {            // Wih [192][64]
      int n = f >> 4, p4 = (f & 15) * 2;
      float4 v = *(const float4*)(wig + (size_t)n * 64 + p4 * 2);
      uint32_t h0, l0, h1, l1;
      split2(v.x, v.y, h0, l0); split2(v.z, v.w, h1, l1);
      smu[WIHH + n * 36 + p4] = h0; smu[WIHH + n * 36 + p4 + 1] = h1;
      smu[WIHL + n * 36 + p4] = l0; smu[WIHL + n * 36 + p4 + 1] = l1;
    }
    const float* whg = Whh + (size_t)a * 192 * 64;
    #pragma unroll 2
    for (int f = tid; f < 3072; f += NT) {            // Whh [192][64]
      int n = f >> 4, p4 = (f & 15) * 2;
      float4 v = *(const float4*)(whg + (size_t)n * 64 + p4 * 2);
      uint32_t h0, l0, h1, l1;
      split2(v.x, v.y, h0, l0); split2(v.z, v.w, h1, l1);
      smu[WHH_H + n * 36 + p4] = h0; smu[WHH_H + n * 36 + p4 + 1] = h1;
      smu[WHH_L + n * 36 + p4] = l0; smu[WHH_L + n * 36 + p4 + 1] = l1;
    }
    const float* w2g = W2 + (size_t)a * 16 * 64;
    for (int f = tid; f < 256; f += NT) {             // W2 [16][64]
      int n = f >> 4, p4 = (f & 15) * 2;
      float4 v = *(const float4*)(w2g + (size_t)n * 64 + p4 * 2);
      uint32_t h0, l0, h1, l1;
      split2(v.x, v.y, h0, l0); split2(v.z, v.w, h1, l1);
      smu[W2H + n * 36 + p4] = h0; smu[W2H + n * 36 + p4 + 1] = h1;
      smu[W2L + n * 36 + p4] = l0; smu[W2L + n * 36 + p4 + 1] = l1;
    }
  }

  // ================= prologue: load first tile's X, h =================
  {
    const int b0 = blockIdx.x * BB;
    const float* xg = inputs + ((size_t)b0 * 8 + a) * 128;
    #pragma unroll 4
    for (int f = tid; f < 2048; f += NT) {            // X [64][128]
      int row = f >> 5, p4 = (f & 31) * 2;
      float4 v = *(const float4*)(xg + (size_t)row * 1024 + p4 * 2);
      uint32_t h0, l0, h1, l1;
      split2(v.x, v.y, h0, l0); split2(v.z, v.w, h1, l1);
      smu[XH + row * 68 + p4] = h0; smu[XH + row * 68 + p4 + 1] = h1;
      smu[XL + row * 68 + p4] = l0; smu[XL + row * 68 + p4 + 1] = l1;
    }
    const float* hg = hidden + ((size_t)b0 * 8 + a) * 64;
    #pragma unroll 2
    for (int f = tid; f < 1024; f += NT) {            // h [64][64]
      int row = f >> 4, p4 = (f & 15) * 2;
      float4 v = *(const float4*)(hg + (size_t)row * 512 + p4 * 2);
      uint32_t h0, l0, h1, l1;
      split2(v.x, v.y, h0, l0); split2(v.z, v.w, h1, l1);
      smu[HHq + row * 36 + p4] = h0; smu[HHq + row * 36 + p4 + 1] = h1;
      smu[HLq + row * 36 + p4] = l0; smu[HLq + row * 36 + p4 + 1] = l1;
    }
  }
  __syncthreads();

  // ================= pipelined tile loop (group-scoped barriers) =================
  const int G = gridDim.x;

  for (int t = blockIdx.x; t < TOTAL_TILES; t += G) {
    const int b0 = t * BB;
    const int tn = t + G;
    const bool have_next = tn < TOTAL_TILES;
    const int bn = tn * BB;

    // ---- prefetch next tile's X / h at LOOP TOP (max LDG latency cover) ----
    float4 pfx[4], pfh[4];
    if (have_next) {
      const float* xg = inputs + ((size_t)bn * 8 + a) * 128;
      #pragma unroll
      for (int k = 0; k < 4; ++k) {
        int f = gl + k * 128;                 // 0..511 within group
        int row = 16 * mw + (f >> 5), p4 = (f & 31) * 2;
        pfx[k] = *(const float4*)(xg + (size_t)row * 1024 + p4 * 2);
      }
      if (nw >= 2) {
        const float* hg = hidden + ((size_t)bn * 8 + a) * 64;
        #pragma unroll
        for (int k = 0; k < 4; ++k) {
          int f = gl2 + k * 64;               // 0..255 within group
          int row = 16 * mw + (f >> 4), p4 = (f & 15) * 2;
          pfh[k] = *(const float4*)(hg + (size_t)row * 512 + p4 * 2);
        }
      }
    }

    // ---- stage 1: z1 = relu(X @ W1^T + b1); even/odd-kc accumulator split ----
    float acc1e[2][4], acc1o[2][4];
    #pragma unroll
    for (int s = 0; s < 2; ++s)
      #pragma unroll
      for (int e = 0; e < 4; ++e) { acc1e[s][e] = 0.f; acc1o[s][e] = 0.f; }

    #pragma unroll
    for (int kc = 0; kc < 8; ++kc) {
      float (*acc)[4] = (kc & 1) ? acc1o : acc1e;
      uint32_t ah[4], al[4];
      uint32_t aoff = (uint32_t)(16 * mw + l15) * 68 + kc * 8 + lhalf * 4;
      ldsm4(ah, sb + 4 * (XH + aoff));
      ldsm4(al, sb + 4 * (XL + aoff));
      #pragma unroll
      for (int s = 0; s < 2; ++s) {
        uint32_t boff = (uint32_t)(8 * (nw + 4 * s) + l7) * 68 + kc * 8 + l8b * 4;
        uint32_t bh0, bh1, bl0, bl1;
        ldsm2(bh0, bh1, sb + 4 * (W1H + boff));
        ldsm2(bl0, bl1, sb + 4 * (W1L + boff));
        mma16816(acc[s], ah, bh0, bh1);
        mma16816(acc[s], al, bh0, bh1);
        mma16816(acc[s], ah, bl0, bl1);
      }
    }
    barg(bid);   // A: group's X reads done (z1 overwrites this group's X rows)

    // ---- epilogue 1: bias+relu -> z1 hi/lo (row-consistent alias: stride 68) ----
    #pragma unroll
    for (int s = 0; s < 2; ++s) {
      int ntile = nw + 4 * s;
      int col = 8 * ntile + 2 * cq;
      int pidx = 4 * ntile + cq;              // z1 col word 0..31
      float bx = smf[B1O + col], by = smf[B1O + col + 1];
      #pragma unroll
      for (int sr = 0; sr < 2; ++sr) {
        int row = 16 * mw + g + 8 * sr;
        float v0 = fmaxf(acc1e[s][2 * sr] + acc1o[s][2 * sr] + bx, 0.f);
        float v1 = fmaxf(acc1e[s][2 * sr + 1] + acc1o[s][2 * sr + 1] + by, 0.f);
        uint32_t ph, pl;
        split2(v0, v1, ph, pl);
        smu[XH + row * 68 + pidx] = ph;
        smu[XL + row * 68 + pidx] = pl;
      }
    }
    barg(bid);   // B: group's z1 visible

    // ---- stage 2: gate GEMMs. N-space 256 = [r|z|i_n|h_n]; warp owns ntile = nw + 4j.
    //      r/z gates (j<4): 2-term hi/lo (drop A_hi*B_lo; error absorbed by sigmoid).
    //      i_n/h_n (j>=4): full 3-term. ----
    float acc2[8][4];
    #pragma unroll
    for (int j = 0; j < 8; ++j)
      #pragma unroll
      for (int e = 0; e < 4; ++e) acc2[j][e] = 0.f;

    #pragma unroll
    for (int kc = 0; kc < 4; ++kc) {
      uint32_t zh[4], zl[4], hh_[4], hl_[4];
      uint32_t zoff = (uint32_t)(16 * mw + l15) * 68 + kc * 8 + lhalf * 4;  // z1: stride 68
      uint32_t aoff = (uint32_t)(16 * mw + l15) * 36 + kc * 8 + lhalf * 4;  // h: stride 36
      ldsm4(zh, sb + 4 * (XH + zoff));
      ldsm4(zl, sb + 4 * (XL + zoff));
      ldsm4(hh_, sb + 4 * (HHq + aoff));
      ldsm4(hl_, sb + 4 * (HLq + aoff));
      uint32_t bbase = (uint32_t)l7 * 36 + kc * 8 + l8b * 4;
      #pragma unroll
      for (int j = 0; j < 8; ++j) {
        int ntile = nw + 4 * j;
        if (j < 4) {                        // r/z gates: 2-term, Wih + Whh
          uint32_t bh0, bh1;
          uint32_t o = (uint32_t)(8 * ntile) * 36 + bbase;
          ldsm2(bh0, bh1, sb + 4 * (WIHH + o));
          mma16816(acc2[j], zh, bh0, bh1);
          mma16816(acc2[j], zl, bh0, bh1);
          uint32_t hb0, hb1;
          ldsm2(hb0, hb1, sb + 4 * (WHH_H + o));
          mma16816(acc2[j], hh_, hb0, hb1);
          mma16816(acc2[j], hl_, hb0, hb1);
        } else if (ntile < 24) {            // i_n: z1 @ Wih rows 8*ntile, 3-term
          uint32_t bh0, bh1, bl0, bl1;
          uint32_t o = (uint32_t)(8 * ntile) * 36 + bbase;
          ldsm2(bh0, bh1, sb + 4 * (WIHH + o));
          ldsm2(bl0, bl1, sb + 4 * (WIHL + o));
          mma16816(acc2[j], zh, bh0, bh1);
          mma16816(acc2[j], zl, bh0, bh1);
          mma16816(acc2[j], zh, bl0, bl1);
        } else {                            // h_n: h @ Whh rows 8*ntile-64, 3-term
          int n0 = 8 * ntile - 64;
          uint32_t bh0, bh1, bl0, bl1;
          uint32_t o = (uint32_t)n0 * 36 + bbase;
          ldsm2(bh0, bh1, sb + 4 * (WHH_H + o));
          ldsm2(bl0, bl1, sb + 4 * (WHH_L + o));
          mma16816(acc2[j], hh_, bh0, bh1);
          mma16816(acc2[j], hl_, bh0, bh1);
          mma16816(acc2[j], hh_, bl0, bl1);
        }
      }
    }
    barg(bid);   // C: group's z1 / h reads done

    // ---- epilogue 2: GRU -> h_new (+gmem); store next X (group rows) ----
    #pragma unroll
    for (int s = 0; s < 2; ++s) {
      int ntile = nw + 4 * s;
      int cb = 8 * ntile + 2 * cq;
      int pidx = 4 * ntile + cq;
      float brv0 = smf[BRO + cb],  brv1 = smf[BRO + cb + 1];
      float bzv0 = smf[BZO + cb],  bzv1 = smf[BZO + cb + 1];
      float biv0 = smf[BINO + cb], biv1 = smf[BINO + cb + 1];
      float bnv0 = smf[BHNO + cb], bnv1 = smf[BHNO + cb + 1];
      #pragma unroll
      for (int sr = 0; sr < 2; ++sr) {
        int row = 16 * mw + g + 8 * sr;
        uint32_t uh = smu[HHq + row * 36 + pidx], ul = smu[HLq + row * 36 + pidx];
        float ho0 = bfbits2f(uh & 0xffffu) + bfbits2f(ul & 0xffffu);
        float ho1 = bfbits2f(uh >> 16) + bfbits2f(ul >> 16);
        float rv0 = sigm(acc2[s][2 * sr] + brv0);
        float rv1 = sigm(acc2[s][2 * sr + 1] + brv1);
        float zv0 = sigm(acc2[2 + s][2 * sr] + bzv0);
        float zv1 = sigm(acc2[2 + s][2 * sr + 1] + bzv1);
        float nv0 = tanh_(acc2[4 + s][2 * sr] + biv0 +
                          rv0 * (acc2[6 + s][2 * sr] + bnv0));
        float nv1 = tanh_(acc2[4 + s][2 * sr + 1] + biv1 +
                          rv1 * (acc2[6 + s][2 * sr + 1] + bnv1));
        float hn0 = nv0 + zv0 * (ho0 - nv0);
        float hn1 = nv1 + zv1 * (ho1 - nv1);
        uint32_t ph, pl;
        split2(hn0, hn1, ph, pl);
        smu[HNH + row * 36 + pidx] = ph;
        smu[HNL + row * 36 + pidx] = pl;
        *(float2*)(out_h + ((size_t)(b0 + row) * 8 + a) * 64 + cb) = make_float2(hn0, hn1);
      }
    }
    if (have_next) {
      #pragma unroll
      for (int k = 0; k < 4; ++k) {
        int f = gl + k * 128;
        int row = 16 * mw + (f >> 5), p4 = (f & 31) * 2;
        uint32_t h0, l0, h1, l1;
        split2(pfx[k].x, pfx[k].y, h0, l0); split2(pfx[k].z, pfx[k].w, h1, l1);
        smu[XH + row * 68 + p4] = h0; smu[XH + row * 68 + p4 + 1] = h1;
        smu[XL + row * 68 + p4] = l0; smu[XL + row * 68 + p4 + 1] = l1;
      }
    }
    barg(bid);   // D: group's hn + next-X visible

    // ---- stage 3 (n-warps 0,1, even/odd-kc split) || next-h store (n-warps 2,3) ----
    if (nw < 2) {
      float acc3e[4] = {0.f, 0.f, 0.f, 0.f};
      float acc3o[4] = {0.f, 0.f, 0.f, 0.f};
      #pragma unroll
      for (int kc = 0; kc < 4; ++kc) {
        float* acc = (kc & 1) ? acc3o : acc3e;
        uint32_t boff = (uint32_t)(8 * nw + l7) * 36 + kc * 8 + l8b * 4;
        uint32_t bh0, bh1, bl0, bl1;
        ldsm2(bh0, bh1, sb + 4 * (W2H + boff));
        ldsm2(bl0, bl1, sb + 4 * (W2L + boff));
        uint32_t aoff = (uint32_t)(16 * mw + l15) * 36 + kc * 8 + lhalf * 4;
        uint32_t ah[4], al[4];
        ldsm4(ah, sb + 4 * (HNH + aoff));
        ldsm4(al, sb + 4 * (HNL + aoff));
        mma16816(acc, ah, bh0, bh1);
        mma16816(acc, al, bh0, bh1);
        mma16816(acc, ah, bl0, bl1);
      }
      int colb = 8 * nw + 2 * cq;
      float bq0 = smf[B2O + colb], bq1 = smf[B2O + colb + 1];
      #pragma unroll
      for (int sr = 0; sr < 2; ++sr) {
        int row = 16 * mw + g + 8 * sr;
        float q0 = acc3e[2 * sr] + acc3o[2 * sr] + bq0;
        float q1 = acc3e[2 * sr + 1] + acc3o[2 * sr + 1] + bq1;
        *(float2*)(out_q + ((size_t)(b0 + row) * 8 + a) * 16 + colb) = make_float2(q0, q1);
      }
    } else if (have_next) {
      #pragma unroll
      for (int k = 0; k < 4; ++k) {
        int f = gl2 + k * 64;
        int row = 16 * mw + (f >> 4), p4 = (f & 15) * 2;
        uint32_t h0, l0, h1, l1;
        split2(pfh[k].x, pfh[k].y, h0, l0); split2(pfh[k].z, pfh[k].w, h1, l1);
        smu[HHq + row * 36 + p4] = h0; smu[HHq + row * 36 + p4 + 1] = h1;
        smu[HLq + row * 36 + p4] = l0; smu[HLq + row * 36 + p4 + 1] = l1;
      }
    }
  }
}

extern "C" void kernel_launch(void* const* d_in, const int* in_sizes, int n_in,
                              void* d_out, int out_size) {
  (void)n_in; (void)out_size;
  const float* inputs = (const float*)d_in[0];
  const float* hidden = (const float*)d_in[1];
  const float* W1  = (const float*)d_in[2];
  const float* b1  = (const float*)d_in[3];
  const float* Wih = (const float*)d_in[4];
  const float* bih = (const float*)d_in[5];
  const float* Whh = (const float*)d_in[6];
  const float* bhh = (const float*)d_in[7];
  const float* W2  = (const float*)d_in[8];
  const float* b2  = (const float*)d_in[9];

  const int B = in_sizes[0] / (8 * 128);   // 16384
  float* out_q = (float*)d_out;
  float* out_h = out_q + (size_t)B * 8 * 16;

  const size_t smem = (size_t)SMEM_WORDS * 4;   // 223104 B
  cudaFuncSetAttribute(rnn_v17_kernel,
                       cudaFuncAttributeMaxDynamicSharedMemorySize, (int)smem);
  dim3 grid(18, 8, 1);                          // 144 CTAs, strided tiles
  rnn_v17_kernel<<<grid, NT, smem>>>(inputs, hidden, W1, b1, Wih, bih,
                                     Whh, bhh, W2, b2, out_q, out_h);
}